// round 1
// baseline (speedup 1.0000x reference)
#include <cuda_runtime.h>

#define T_TOK 4096
#define DIM   512
#define FDIM  2048
#define NEXP  8
#define EPSV  1e-8f

#define TM 128
#define TN 128
#define TK 16

// -------- scratch (static device globals; no runtime alloc) --------
__device__ float g_anchors_n[NEXP * DIM];
__device__ int   g_cnt[NEXP];
__device__ int   g_off[NEXP];
__device__ int   g_tok[NEXP][T_TOK];
__device__ float g_gate[NEXP][T_TOK];
__device__ float g_H[(2 * T_TOK) * FDIM];   // 8192 x 2048 fp32 = 67 MB

// -------- packed f32x2 helpers --------
__device__ __forceinline__ unsigned long long pack2(float a) {
    unsigned long long r;
    asm("mov.b64 %0, {%1, %1};" : "=l"(r) : "f"(a));
    return r;
}
__device__ __forceinline__ unsigned long long fma2(unsigned long long a,
                                                   unsigned long long b,
                                                   unsigned long long c) {
    unsigned long long d;
    asm("fma.rn.f32x2 %0, %1, %2, %3;" : "=l"(d) : "l"(a), "l"(b), "l"(c));
    return d;
}

// -------- kernel: zero output + reset counters --------
__global__ void k_zero(float* __restrict__ out) {
    int i = blockIdx.x * blockDim.x + threadIdx.x;      // 2048*256 = 524288 float4
    ((float4*)out)[i] = make_float4(0.f, 0.f, 0.f, 0.f);
    if (blockIdx.x == 0 && threadIdx.x < NEXP) g_cnt[threadIdx.x] = 0;
}

// -------- kernel: normalize anchors --------
__global__ void k_anchors(const float* __restrict__ A, float* __restrict__ an_out,
                          int write_an) {
    int w = threadIdx.x >> 5, lane = threadIdx.x & 31;
    float ss = 0.f;
    for (int d = lane; d < DIM; d += 32) { float v = A[w * DIM + d]; ss += v * v; }
    #pragma unroll
    for (int o = 16; o; o >>= 1) ss += __shfl_xor_sync(0xffffffffu, ss, o);
    float inv = 1.f / fmaxf(sqrtf(ss), EPSV);
    for (int d = lane; d < DIM; d += 32) {
        float v = A[w * DIM + d] * inv;
        g_anchors_n[w * DIM + d] = v;
        if (write_an) an_out[w * DIM + d] = v;
    }
}

// -------- kernel: routing (scores, top2, gates, dispatch) --------
__global__ void k_route(const float* __restrict__ x,
                        float* __restrict__ scores_out,
                        float* __restrict__ idx_out, int wflags) {
    int wid = (blockIdx.x * blockDim.x + threadIdx.x) >> 5;   // token
    int lane = threadIdx.x & 31;
    if (wid >= T_TOK) return;
    const float* xr = x + (size_t)wid * DIM;
    float xx = 0.f;
    float dt[NEXP];
    #pragma unroll
    for (int e = 0; e < NEXP; e++) dt[e] = 0.f;
    for (int d = lane; d < DIM; d += 32) {
        float xv = xr[d];
        xx += xv * xv;
        #pragma unroll
        for (int e = 0; e < NEXP; e++) dt[e] += xv * g_anchors_n[e * DIM + d];
    }
    #pragma unroll
    for (int o = 16; o; o >>= 1) {
        xx += __shfl_xor_sync(0xffffffffu, xx, o);
        #pragma unroll
        for (int e = 0; e < NEXP; e++) dt[e] += __shfl_xor_sync(0xffffffffu, dt[e], o);
    }
    if (lane == 0) {
        float inv = 1.f / fmaxf(sqrtf(xx), EPSV);
        float s[NEXP];
        #pragma unroll
        for (int e = 0; e < NEXP; e++) s[e] = dt[e] * inv;
        int i1 = 0; float v1 = s[0];
        #pragma unroll
        for (int e = 1; e < NEXP; e++) if (s[e] > v1) { v1 = s[e]; i1 = e; }
        int i2 = -1; float v2 = -1e30f;
        #pragma unroll
        for (int e = 0; e < NEXP; e++) if (e != i1 && s[e] > v2) { v2 = s[e]; i2 = e; }
        float e2 = expf(v2 - v1);
        float denom = 1.f / (1.f + e2);
        float g1 = denom, g2 = e2 * denom;
        int s1 = atomicAdd(&g_cnt[i1], 1);
        g_tok[i1][s1] = wid; g_gate[i1][s1] = g1;
        int s2 = atomicAdd(&g_cnt[i2], 1);
        g_tok[i2][s2] = wid; g_gate[i2][s2] = g2;
        if (wflags & 1) {
            #pragma unroll
            for (int e = 0; e < NEXP; e++) scores_out[wid * NEXP + e] = s[e];
        }
        if (wflags & 2) {
            idx_out[wid * 2 + 0] = (float)i1;
            idx_out[wid * 2 + 1] = (float)i2;
        }
    }
}

// -------- kernel: tiny exclusive scan of counts --------
__global__ void k_offsets() {
    int o = 0;
    for (int e = 0; e < NEXP; e++) { g_off[e] = o; o += g_cnt[e]; }
}

// -------- kernel: GEMM1  H = gelu(Xg @ W1[e] + b1[e]) --------
__global__ __launch_bounds__(256, 2)
void k_gemm1(const float* __restrict__ x, const float* __restrict__ W1,
             const float* __restrict__ b1) {
    const int e = blockIdx.z;
    const int count = g_cnt[e];
    const int m0 = blockIdx.y * TM;
    if (m0 >= count) return;
    const int n0 = blockIdx.x * TN;
    const int base = g_off[e];
    const int tid = threadIdx.x;

    __shared__ __align__(16) float As[TK][TM + 4];
    __shared__ __align__(16) float Bs[TK][TN + 4];
    __shared__ int toks[TM];
    if (tid < TM) {
        int mi = m0 + tid;
        toks[tid] = (mi < count) ? g_tok[e][mi] : -1;
    }
    __syncthreads();

    const int tx = tid & 15, ty = tid >> 4;
    unsigned long long acc[8][4];
    #pragma unroll
    for (int i = 0; i < 8; i++)
        #pragma unroll
        for (int j = 0; j < 4; j++) acc[i][j] = 0ull;

    const float* Wb = W1 + (size_t)e * DIM * FDIM + n0;

    for (int k0 = 0; k0 < DIM; k0 += TK) {
        #pragma unroll
        for (int j = 0; j < 2; j++) {                       // A: 128x16
            int q = tid + j * 256;
            int m = q >> 2, kq = q & 3;
            int tok = toks[m];
            float4 v = make_float4(0.f, 0.f, 0.f, 0.f);
            if (tok >= 0) v = *(const float4*)(x + (size_t)tok * DIM + k0 + kq * 4);
            As[kq * 4 + 0][m] = v.x; As[kq * 4 + 1][m] = v.y;
            As[kq * 4 + 2][m] = v.z; As[kq * 4 + 3][m] = v.w;
        }
        #pragma unroll
        for (int j = 0; j < 2; j++) {                       // B: 16x128
            int q = tid + j * 256;
            int kk = q >> 5, nq = q & 31;
            float4 v = *(const float4*)(Wb + (size_t)(k0 + kk) * FDIM + nq * 4);
            *(float4*)&Bs[kk][nq * 4] = v;
        }
        __syncthreads();
        #pragma unroll
        for (int k = 0; k < TK; k++) {
            float4 a0 = *(float4*)&As[k][ty * 4];
            float4 a1 = *(float4*)&As[k][64 + ty * 4];
            float4 b0 = *(float4*)&Bs[k][tx * 4];
            float4 b1r = *(float4*)&Bs[k][64 + tx * 4];
            unsigned long long bb[4];
            bb[0] = ((const unsigned long long*)&b0)[0];
            bb[1] = ((const unsigned long long*)&b0)[1];
            bb[2] = ((const unsigned long long*)&b1r)[0];
            bb[3] = ((const unsigned long long*)&b1r)[1];
            float av[8] = {a0.x, a0.y, a0.z, a0.w, a1.x, a1.y, a1.z, a1.w};
            #pragma unroll
            for (int i = 0; i < 8; i++) {
                unsigned long long aa = pack2(av[i]);
                #pragma unroll
                for (int jj = 0; jj < 4; jj++) acc[i][jj] = fma2(aa, bb[jj], acc[i][jj]);
            }
        }
        __syncthreads();
    }

    #pragma unroll
    for (int i = 0; i < 8; i++) {
        int mloc = (i < 4) ? (ty * 4 + i) : (64 + ty * 4 + (i - 4));
        int mi = m0 + mloc;
        if (mi >= count) continue;
        float* Hrow = g_H + (size_t)(base + mi) * FDIM + n0;
        #pragma unroll
        for (int jj = 0; jj < 4; jj++) {
            int nloc = (jj < 2) ? (tx * 4 + jj * 2) : (64 + tx * 4 + (jj - 2) * 2);
            float2 v = *(float2*)&acc[i][jj];
            float h0 = v.x + b1[e * FDIM + n0 + nloc];
            float h1 = v.y + b1[e * FDIM + n0 + nloc + 1];
            h0 = 0.5f * h0 * (1.f + erff(h0 * 0.7071067811865476f));
            h1 = 0.5f * h1 * (1.f + erff(h1 * 0.7071067811865476f));
            *(float2*)(Hrow + nloc) = make_float2(h0, h1);
        }
    }
}

// -------- kernel: GEMM2  out += gate * (H @ W2[e] + b2[e]) --------
__global__ __launch_bounds__(256, 2)
void k_gemm2(const float* __restrict__ W2, const float* __restrict__ b2,
             float* __restrict__ out) {
    const int e = blockIdx.z;
    const int count = g_cnt[e];
    const int m0 = blockIdx.y * TM;
    if (m0 >= count) return;
    const int n0 = blockIdx.x * TN;
    const int base = g_off[e];
    const int tid = threadIdx.x;

    __shared__ __align__(16) float As[TK][TM + 4];
    __shared__ __align__(16) float Bs[TK][TN + 4];
    __shared__ int   toks[TM];
    __shared__ float gsh[TM];
    __shared__ int   rows[TM];
    if (tid < TM) {
        int mi = m0 + tid;
        if (mi < count) {
            toks[tid] = g_tok[e][mi];
            gsh[tid]  = g_gate[e][mi];
            rows[tid] = base + mi;
        } else {
            toks[tid] = -1; gsh[tid] = 0.f; rows[tid] = -1;
        }
    }
    __syncthreads();

    const int tx = tid & 15, ty = tid >> 4;
    unsigned long long acc[8][4];
    #pragma unroll
    for (int i = 0; i < 8; i++)
        #pragma unroll
        for (int j = 0; j < 4; j++) acc[i][j] = 0ull;

    const float* Wb = W2 + (size_t)e * FDIM * DIM + n0;

    for (int k0 = 0; k0 < FDIM; k0 += TK) {
        #pragma unroll
        for (int j = 0; j < 2; j++) {                       // A: 128x16 from g_H
            int q = tid + j * 256;
            int m = q >> 2, kq = q & 3;
            int row = rows[m];
            float4 v = make_float4(0.f, 0.f, 0.f, 0.f);
            if (row >= 0) v = *(const float4*)(g_H + (size_t)row * FDIM + k0 + kq * 4);
            As[kq * 4 + 0][m] = v.x; As[kq * 4 + 1][m] = v.y;
            As[kq * 4 + 2][m] = v.z; As[kq * 4 + 3][m] = v.w;
        }
        #pragma unroll
        for (int j = 0; j < 2; j++) {                       // B: 16x128
            int q = tid + j * 256;
            int kk = q >> 5, nq = q & 31;
            float4 v = *(const float4*)(Wb + (size_t)(k0 + kk) * DIM + nq * 4);
            *(float4*)&Bs[kk][nq * 4] = v;
        }
        __syncthreads();
        #pragma unroll
        for (int k = 0; k < TK; k++) {
            float4 a0 = *(float4*)&As[k][ty * 4];
            float4 a1 = *(float4*)&As[k][64 + ty * 4];
            float4 b0 = *(float4*)&Bs[k][tx * 4];
            float4 b1r = *(float4*)&Bs[k][64 + tx * 4];
            unsigned long long bb[4];
            bb[0] = ((const unsigned long long*)&b0)[0];
            bb[1] = ((const unsigned long long*)&b0)[1];
            bb[2] = ((const unsigned long long*)&b1r)[0];
            bb[3] = ((const unsigned long long*)&b1r)[1];
            float av[8] = {a0.x, a0.y, a0.z, a0.w, a1.x, a1.y, a1.z, a1.w};
            #pragma unroll
            for (int i = 0; i < 8; i++) {
                unsigned long long aa = pack2(av[i]);
                #pragma unroll
                for (int jj = 0; jj < 4; jj++) acc[i][jj] = fma2(aa, bb[jj], acc[i][jj]);
            }
        }
        __syncthreads();
    }

    #pragma unroll
    for (int i = 0; i < 8; i++) {
        int mloc = (i < 4) ? (ty * 4 + i) : (64 + ty * 4 + (i - 4));
        int mi = m0 + mloc;
        if (mi >= count) continue;
        int tok = toks[mloc];
        float g = gsh[mloc];
        float* orow = out + (size_t)tok * DIM + n0;
        #pragma unroll
        for (int jj = 0; jj < 4; jj++) {
            int nloc = (jj < 2) ? (tx * 4 + jj * 2) : (64 + tx * 4 + (jj - 2) * 2);
            float2 v = *(float2*)&acc[i][jj];
            float y0 = v.x + b2[e * DIM + n0 + nloc];
            float y1 = v.y + b2[e * DIM + n0 + nloc + 1];
            atomicAdd(orow + nloc,     g * y0);
            atomicAdd(orow + nloc + 1, g * y1);
        }
    }
}

// -------- launch --------
extern "C" void kernel_launch(void* const* d_in, const int* in_sizes, int n_in,
                              void* d_out, int out_size) {
    const float* x       = (const float*)d_in[0];
    const float* anchors = (const float*)d_in[1];
    const float* W1      = (const float*)d_in[2];
    const float* b1      = (const float*)d_in[3];
    const float* W2      = (const float*)d_in[4];
    const float* b2      = (const float*)d_in[5];
    float* out = (float*)d_out;

    const int OUT_END = T_TOK * DIM;             // 2097152
    const int AN_END  = OUT_END + NEXP * DIM;    // 2101248
    const int SC_END  = AN_END + T_TOK * NEXP;   // 2134016
    const int IX_END  = SC_END + T_TOK * 2;      // 2142208
    int write_an = (out_size >= AN_END) ? 1 : 0;
    int wflags = ((out_size >= SC_END) ? 1 : 0) | ((out_size >= IX_END) ? 2 : 0);

    k_zero<<<2048, 256>>>(out);
    k_anchors<<<1, 256>>>(anchors, out + OUT_END, write_an);
    k_route<<<512, 256>>>(x, out + AN_END, out + SC_END, wflags);
    k_offsets<<<1, 1>>>();
    dim3 g1(FDIM / TN, (T_TOK + TM - 1) / TM, NEXP);
    k_gemm1<<<g1, 256>>>(x, W1, b1);
    dim3 g2(DIM / TN, (T_TOK + TM - 1) / TM, NEXP);
    k_gemm2<<<g2, 256>>>(W2, b2, out);
}

// round 3
// speedup vs baseline: 1.5591x; 1.5591x over previous
#include <cuda_runtime.h>
#include <cstdint>

#define T_TOK 4096
#define DIM   512
#define FDIM  2048
#define NEXP  8
#define EPSV  1e-8f

#define TM   128
#define TN   128
#define KC   32
#define SMEM_STAGE 65536
#define SMEM_DYN   (2 * SMEM_STAGE + 1024)

#if defined(__CUDA_ARCH__) && defined(__CUDA_ARCH_FEAT_SM103_ALL)
#define USE_TC 1
#else
#define USE_TC 0
#endif

// -------- scratch (static device globals; no runtime alloc) --------
__device__ float g_anchors_n[NEXP * DIM];
__device__ int   g_cnt[NEXP];
__device__ int   g_off[NEXP];
__device__ int   g_tok[NEXP][T_TOK];
__device__ float g_gate[NEXP][T_TOK];
__device__ float g_H[(2 * T_TOK) * FDIM];   // 8192 x 2048 fp32

// ==================== helpers ====================
__device__ __forceinline__ float gelu_f(float h) {
    return 0.5f * h * (1.f + erff(h * 0.7071067811865476f));
}
__device__ __forceinline__ unsigned long long pack2(float a) {
    unsigned long long r;
    asm("mov.b64 %0, {%1, %1};" : "=l"(r) : "f"(a));
    return r;
}
__device__ __forceinline__ unsigned long long fma2(unsigned long long a,
                                                   unsigned long long b,
                                                   unsigned long long c) {
    unsigned long long d;
    asm("fma.rn.f32x2 %0, %1, %2, %3;" : "=l"(d) : "l"(a), "l"(b), "l"(c));
    return d;
}

#if USE_TC
__device__ __forceinline__ uint32_t sm2u32(const void* p) {
    uint32_t a;
    asm("{ .reg .u64 t; cvta.to.shared.u64 t, %1; cvt.u32.u64 %0, t; }" : "=r"(a) : "l"(p));
    return a;
}
__device__ __forceinline__ bool elect1() {
    uint32_t r;
    asm volatile("{ .reg .pred p; elect.sync _|p, 0xFFFFFFFF; selp.b32 %0, 1, 0, p; }" : "=r"(r));
    return r != 0;
}
__device__ __forceinline__ void split_tf32(float f, float& hi, float& lo) {
    uint32_t u;
    asm("cvt.rna.tf32.f32 %0, %1;" : "=r"(u) : "f"(f));
    hi = __uint_as_float(u);
    float d = f - hi;
    uint32_t v;
    asm("cvt.rna.tf32.f32 %0, %1;" : "=r"(v) : "f"(d));
    lo = __uint_as_float(v);
}
__device__ __forceinline__ void sts128(uint32_t a, float x, float y, float z, float w) {
    asm volatile("st.shared.v4.b32 [%0], {%1,%2,%3,%4};"
                 :: "r"(a), "f"(x), "f"(y), "f"(z), "f"(w) : "memory");
}
__device__ __forceinline__ void mbar_init(uint32_t a, uint32_t c) {
    asm volatile("mbarrier.init.shared.b64 [%0], %1;" :: "r"(a), "r"(c) : "memory");
}
__device__ __forceinline__ void mbar_inval(uint32_t a) {
    asm volatile("mbarrier.inval.shared.b64 [%0];" :: "r"(a) : "memory");
}
__device__ __forceinline__ void mbar_wait(uint32_t a, uint32_t ph) {
    uint32_t done;
    asm volatile("{\n\t.reg .pred p;\n\t"
                 "mbarrier.try_wait.parity.acquire.cta.shared::cta.b64 p, [%1], %2;\n\t"
                 "selp.b32 %0, 1, 0, p;\n\t}"
                 : "=r"(done) : "r"(a), "r"(ph) : "memory");
    if (!done) {
        asm volatile("{\n\t.reg .pred P1;\n\t"
                     "LW%=:\n\t"
                     "mbarrier.try_wait.parity.acquire.cta.shared::cta.b64 P1, [%0], %1, 0x989680;\n\t"
                     "@P1 bra.uni LD%=;\n\t"
                     "bra.uni LW%=;\n\t"
                     "LD%=:\n\t}"
                     :: "r"(a), "r"(ph) : "memory");
    }
}
__device__ __forceinline__ void tc_commit(uint32_t mb) {
    asm volatile("tcgen05.commit.cta_group::1.mbarrier::arrive::one.shared::cluster.b64 [%0];"
                 :: "r"(mb) : "memory");
}
__device__ __forceinline__ void mma_tf32(uint32_t d, uint64_t a, uint64_t b,
                                         uint32_t idesc, uint32_t en) {
    asm volatile("{\n\t.reg .pred p;\n\tsetp.ne.u32 p, %4, 0;\n\t"
                 "tcgen05.mma.cta_group::1.kind::tf32 [%0], %1, %2, %3, {%5,%5,%5,%5}, p;\n\t}"
                 :: "r"(d), "l"(a), "l"(b), "r"(idesc), "r"(en), "r"(0u) : "memory");
}
#define LDTM32(r, ta) \
    asm volatile( \
        "tcgen05.ld.sync.aligned.32x32b.x32.b32 " \
        "{%0, %1, %2, %3, %4, %5, %6, %7, " \
        " %8, %9, %10, %11, %12, %13, %14, %15, " \
        " %16, %17, %18, %19, %20, %21, %22, %23, " \
        " %24, %25, %26, %27, %28, %29, %30, %31}, [%32];" \
        : "=r"((r)[0]),  "=r"((r)[1]),  "=r"((r)[2]),  "=r"((r)[3]), \
          "=r"((r)[4]),  "=r"((r)[5]),  "=r"((r)[6]),  "=r"((r)[7]), \
          "=r"((r)[8]),  "=r"((r)[9]),  "=r"((r)[10]), "=r"((r)[11]), \
          "=r"((r)[12]), "=r"((r)[13]), "=r"((r)[14]), "=r"((r)[15]), \
          "=r"((r)[16]), "=r"((r)[17]), "=r"((r)[18]), "=r"((r)[19]), \
          "=r"((r)[20]), "=r"((r)[21]), "=r"((r)[22]), "=r"((r)[23]), \
          "=r"((r)[24]), "=r"((r)[25]), "=r"((r)[26]), "=r"((r)[27]), \
          "=r"((r)[28]), "=r"((r)[29]), "=r"((r)[30]), "=r"((r)[31]) \
        : "r"(ta))

__device__ __forceinline__ uint64_t mk_desc(uint32_t addr) {
    // SW128, version=1 (Blackwell), SBO=64, LBO=1
    return ((uint64_t)2 << 61) | ((uint64_t)1 << 46) | ((uint64_t)64 << 32) |
           ((uint64_t)1 << 16) | ((uint64_t)(addr >> 4) & 0x3FFF);
}
__device__ __forceinline__ uint32_t swoff(int r, int c16) {
    return (uint32_t)(((r >> 3) << 10) + ((r & 7) << 7) + (((c16 ^ (r & 7)) & 7) << 4));
}
// idesc: c=F32(1), a=TF32(2), b=TF32(2), N=128, M=128
#define IDESC ((1u << 4) | (2u << 7) | (2u << 10) | ((TN / 8) << 17) | ((TM / 16) << 24))
#endif  // USE_TC

// ==================== small kernels ====================
__global__ void k_zero(float* __restrict__ out) {
    int i = blockIdx.x * blockDim.x + threadIdx.x;
    ((float4*)out)[i] = make_float4(0.f, 0.f, 0.f, 0.f);
    if (blockIdx.x == 0 && threadIdx.x < NEXP) g_cnt[threadIdx.x] = 0;
}

__global__ void k_anchors(const float* __restrict__ A, float* __restrict__ an_out,
                          int write_an) {
    int w = threadIdx.x >> 5, lane = threadIdx.x & 31;
    float ss = 0.f;
    for (int d = lane; d < DIM; d += 32) { float v = A[w * DIM + d]; ss += v * v; }
    #pragma unroll
    for (int o = 16; o; o >>= 1) ss += __shfl_xor_sync(0xffffffffu, ss, o);
    float inv = 1.f / fmaxf(sqrtf(ss), EPSV);
    for (int d = lane; d < DIM; d += 32) {
        float v = A[w * DIM + d] * inv;
        g_anchors_n[w * DIM + d] = v;
        if (write_an) an_out[w * DIM + d] = v;
    }
}

__global__ void k_route(const float* __restrict__ x,
                        float* __restrict__ scores_out,
                        float* __restrict__ idx_out, int wflags) {
    int wid = (blockIdx.x * blockDim.x + threadIdx.x) >> 5;
    int lane = threadIdx.x & 31;
    if (wid >= T_TOK) return;
    const float* xr = x + (size_t)wid * DIM;
    float xx = 0.f;
    float dt[NEXP];
    #pragma unroll
    for (int e = 0; e < NEXP; e++) dt[e] = 0.f;
    for (int d = lane; d < DIM; d += 32) {
        float xv = xr[d];
        xx += xv * xv;
        #pragma unroll
        for (int e = 0; e < NEXP; e++) dt[e] += xv * g_anchors_n[e * DIM + d];
    }
    #pragma unroll
    for (int o = 16; o; o >>= 1) {
        xx += __shfl_xor_sync(0xffffffffu, xx, o);
        #pragma unroll
        for (int e = 0; e < NEXP; e++) dt[e] += __shfl_xor_sync(0xffffffffu, dt[e], o);
    }
    if (lane == 0) {
        float inv = 1.f / fmaxf(sqrtf(xx), EPSV);
        float s[NEXP];
        #pragma unroll
        for (int e = 0; e < NEXP; e++) s[e] = dt[e] * inv;
        int i1 = 0; float v1 = s[0];
        #pragma unroll
        for (int e = 1; e < NEXP; e++) if (s[e] > v1) { v1 = s[e]; i1 = e; }
        int i2 = -1; float v2 = -1e30f;
        #pragma unroll
        for (int e = 0; e < NEXP; e++) if (e != i1 && s[e] > v2) { v2 = s[e]; i2 = e; }
        float e2 = expf(v2 - v1);
        float denom = 1.f / (1.f + e2);
        float g1 = denom, g2 = e2 * denom;
        int s1 = atomicAdd(&g_cnt[i1], 1);
        g_tok[i1][s1] = wid; g_gate[i1][s1] = g1;
        int s2 = atomicAdd(&g_cnt[i2], 1);
        g_tok[i2][s2] = wid; g_gate[i2][s2] = g2;
        if (wflags & 1) {
            #pragma unroll
            for (int e = 0; e < NEXP; e++) scores_out[wid * NEXP + e] = s[e];
        }
        if (wflags & 2) {
            idx_out[wid * 2 + 0] = (float)i1;
            idx_out[wid * 2 + 1] = (float)i2;
        }
    }
}

__global__ void k_offsets() {
    int o = 0;
    for (int e = 0; e < NEXP; e++) { g_off[e] = o; o += g_cnt[e]; }
}

// ==================== GEMM1: H = gelu(Xg @ W1[e] + b1[e]) ====================
__global__ __launch_bounds__(256, 1)
void k_gemm1(const float* __restrict__ x, const float* __restrict__ W1,
             const float* __restrict__ b1) {
    const int e = blockIdx.z;
    const int count = g_cnt[e];
    const int m0 = blockIdx.y * TM;
    if (m0 >= count) return;
    const int n0 = blockIdx.x * TN;
    const int base = g_off[e];
    const int tid = threadIdx.x;
    const int wid = tid >> 5, lane = tid & 31;
    extern __shared__ char dynraw[];
    __shared__ int toks[TM];
    if (tid < TM) toks[tid] = g_tok[e][min(m0 + tid, count - 1)];

#if USE_TC
    __shared__ __align__(8) unsigned long long s_mbar[2];
    __shared__ uint32_t s_tmem;
    const uint32_t sm = (sm2u32(dynraw) + 1023u) & ~1023u;
    if (tid == 0) { mbar_init(sm2u32(&s_mbar[0]), 1); mbar_init(sm2u32(&s_mbar[1]), 1); }
    if (wid == 0) {
        asm volatile("tcgen05.alloc.cta_group::1.sync.aligned.shared::cta.b32 [%0], %1;"
                     :: "r"(sm2u32(&s_tmem)), "r"(128u) : "memory");
        asm volatile("tcgen05.relinquish_alloc_permit.cta_group::1.sync.aligned;");
    }
    __syncthreads();
    const uint32_t tmem = s_tmem;
    const uint32_t mb0 = sm2u32(&s_mbar[0]);
    const float* Wbase = W1 + (size_t)e * DIM * FDIM + n0;

    const int NC = DIM / KC;   // 16
    for (int c = 0; c < NC; c++) {
        const int st = c & 1;
        const uint32_t mb = mb0 + st * 8;
        if (c >= 2) mbar_wait(mb, ((c - 2) >> 1) & 1);
        const uint32_t A0 = sm + st * SMEM_STAGE;
        const uint32_t A1 = A0 + 16384, B0 = A0 + 32768, B1 = A0 + 49152;
        const int k0 = c * KC;
        #pragma unroll
        for (int j = 0; j < 4; j++) {                       // A: 128 x 32 (gathered x)
            int q = tid + j * 256;
            int r = q >> 3, k4 = q & 7;
            float4 v = *(const float4*)(x + (size_t)toks[r] * DIM + k0 + k4 * 4);
            float hx, lx, hy, ly, hz, lz, hw, lw;
            split_tf32(v.x, hx, lx); split_tf32(v.y, hy, ly);
            split_tf32(v.z, hz, lz); split_tf32(v.w, hw, lw);
            uint32_t o = swoff(r, k4);
            sts128(A0 + o, hx, hy, hz, hw);
            sts128(A1 + o, lx, ly, lz, lw);
        }
        #pragma unroll
        for (int j = 0; j < 4; j++) {                       // B: 128 x 32 (W1 cols)
            int q = tid + j * 256;
            int n = q & 127, kq = q >> 7;
            const float* wp = Wbase + (size_t)(k0 + kq * 4) * FDIM + n;
            float v0 = wp[0], v1 = wp[FDIM], v2 = wp[2 * FDIM], v3 = wp[3 * FDIM];
            float h0, l0, h1, l1, h2, l2, h3, l3;
            split_tf32(v0, h0, l0); split_tf32(v1, h1, l1);
            split_tf32(v2, h2, l2); split_tf32(v3, h3, l3);
            uint32_t o = swoff(n, kq);
            sts128(B0 + o, h0, h1, h2, h3);
            sts128(B1 + o, l0, l1, l2, l3);
        }
        asm volatile("fence.proxy.async.shared::cta;" ::: "memory");
        __syncthreads();
        if (wid == 0 && elect1()) {
            uint64_t da0 = mk_desc(A0), da1 = mk_desc(A1);
            uint64_t db0 = mk_desc(B0), db1 = mk_desc(B1);
            #pragma unroll
            for (int s = 0; s < 4; s++) {
                mma_tf32(tmem, da0 + s * 2, db0 + s * 2, IDESC, (c | s) ? 1u : 0u);
                mma_tf32(tmem, da0 + s * 2, db1 + s * 2, IDESC, 1u);
                mma_tf32(tmem, da1 + s * 2, db0 + s * 2, IDESC, 1u);
            }
            tc_commit(mb);
        }
    }
    mbar_wait(mb0 + ((NC - 1) & 1) * 8, ((NC - 2) >> 1) & 1);
    asm volatile("tcgen05.fence::after_thread_sync;" ::: "memory");

    const int sp = wid & 3, half = wid >> 2;
    const int mi = m0 + sp * 32 + lane;
    const bool valid = mi < count;
    float* Hrow = g_H + (size_t)(base + (valid ? mi : 0)) * FDIM + n0;
    const float* bp = b1 + (size_t)e * FDIM + n0;
    #pragma unroll
    for (int cb = 0; cb < 2; cb++) {
        const uint32_t c0 = half * 64 + cb * 32;
        uint32_t rg[32];
        LDTM32(rg, tmem + c0);
        asm volatile("tcgen05.wait::ld.sync.aligned;" ::: "memory");
        if (valid) {
            #pragma unroll
            for (int i = 0; i < 32; i += 4) {
                float4 o;
                o.x = gelu_f(__uint_as_float(rg[i + 0]) + bp[c0 + i + 0]);
                o.y = gelu_f(__uint_as_float(rg[i + 1]) + bp[c0 + i + 1]);
                o.z = gelu_f(__uint_as_float(rg[i + 2]) + bp[c0 + i + 2]);
                o.w = gelu_f(__uint_as_float(rg[i + 3]) + bp[c0 + i + 3]);
                *(float4*)(Hrow + c0 + i) = o;
            }
        }
    }
    asm volatile("tcgen05.fence::before_thread_sync;" ::: "memory");
    __syncthreads();
    if (tid == 0) { mbar_inval(mb0); mbar_inval(mb0 + 8); }
    if (wid == 0) {
        asm volatile("tcgen05.dealloc.cta_group::1.sync.aligned.b32 %0, %1;"
                     :: "r"(tmem), "r"(128u));
    }
#else
    // ---------- FFMA f32x2 fallback ----------
    float* As = (float*)dynraw;               // [16][132]
    float* Bs = As + 16 * 132;                // [16][132]
    __syncthreads();
    const int tx = tid & 15, ty = tid >> 4;
    unsigned long long acc[8][4];
    #pragma unroll
    for (int i = 0; i < 8; i++)
        #pragma unroll
        for (int j = 0; j < 4; j++) acc[i][j] = 0ull;
    const float* Wb = W1 + (size_t)e * DIM * FDIM + n0;
    for (int k0 = 0; k0 < DIM; k0 += 16) {
        #pragma unroll
        for (int j = 0; j < 2; j++) {
            int q = tid + j * 256;
            int m = q >> 2, kq = q & 3;
            float4 v = *(const float4*)(x + (size_t)toks[m] * DIM + k0 + kq * 4);
            As[(kq * 4 + 0) * 132 + m] = v.x; As[(kq * 4 + 1) * 132 + m] = v.y;
            As[(kq * 4 + 2) * 132 + m] = v.z; As[(kq * 4 + 3) * 132 + m] = v.w;
        }
        #pragma unroll
        for (int j = 0; j < 2; j++) {
            int q = tid + j * 256;
            int kk = q >> 5, nq = q & 31;
            float4 v = *(const float4*)(Wb + (size_t)(k0 + kk) * FDIM + nq * 4);
            *(float4*)&Bs[kk * 132 + nq * 4] = v;
        }
        __syncthreads();
        #pragma unroll
        for (int k = 0; k < 16; k++) {
            float4 a0 = *(float4*)&As[k * 132 + ty * 4];
            float4 a1 = *(float4*)&As[k * 132 + 64 + ty * 4];
            float4 b0 = *(float4*)&Bs[k * 132 + tx * 4];
            float4 b1r = *(float4*)&Bs[k * 132 + 64 + tx * 4];
            unsigned long long bb[4];
            bb[0] = ((const unsigned long long*)&b0)[0];
            bb[1] = ((const unsigned long long*)&b0)[1];
            bb[2] = ((const unsigned long long*)&b1r)[0];
            bb[3] = ((const unsigned long long*)&b1r)[1];
            float av[8] = {a0.x, a0.y, a0.z, a0.w, a1.x, a1.y, a1.z, a1.w};
            #pragma unroll
            for (int i = 0; i < 8; i++) {
                unsigned long long aa = pack2(av[i]);
                #pragma unroll
                for (int jj = 0; jj < 4; jj++) acc[i][jj] = fma2(aa, bb[jj], acc[i][jj]);
            }
        }
        __syncthreads();
    }
    #pragma unroll
    for (int i = 0; i < 8; i++) {
        int mloc = (i < 4) ? (ty * 4 + i) : (64 + ty * 4 + (i - 4));
        int mi = m0 + mloc;
        if (mi >= count) continue;
        float* Hrow = g_H + (size_t)(base + mi) * FDIM + n0;
        #pragma unroll
        for (int jj = 0; jj < 4; jj++) {
            int nloc = (jj < 2) ? (tx * 4 + jj * 2) : (64 + tx * 4 + (jj - 2) * 2);
            float2 v = *(float2*)&acc[i][jj];
            float h0 = gelu_f(v.x + b1[e * FDIM + n0 + nloc]);
            float h1 = gelu_f(v.y + b1[e * FDIM + n0 + nloc + 1]);
            *(float2*)(Hrow + nloc) = make_float2(h0, h1);
        }
    }
#endif
}

// ==================== GEMM2: out += gate * (H @ W2[e] + b2[e]) ====================
__global__ __launch_bounds__(256, 1)
void k_gemm2(const float* __restrict__ W2, const float* __restrict__ b2,
             float* __restrict__ out) {
    const int e = blockIdx.z;
    const int count = g_cnt[e];
    const int m0 = blockIdx.y * TM;
    if (m0 >= count) return;
    const int n0 = blockIdx.x * TN;
    const int base = g_off[e];
    const int tid = threadIdx.x;
    const int wid = tid >> 5, lane = tid & 31;
    extern __shared__ char dynraw[];
    __shared__ int   toks[TM];
    __shared__ float gts[TM];
    if (tid < TM) {
        int mi = min(m0 + tid, count - 1);
        toks[tid] = g_tok[e][mi];
        gts[tid]  = g_gate[e][mi];
    }

#if USE_TC
    __shared__ __align__(8) unsigned long long s_mbar[2];
    __shared__ uint32_t s_tmem;
    const uint32_t sm = (sm2u32(dynraw) + 1023u) & ~1023u;
    if (tid == 0) { mbar_init(sm2u32(&s_mbar[0]), 1); mbar_init(sm2u32(&s_mbar[1]), 1); }
    if (wid == 0) {
        asm volatile("tcgen05.alloc.cta_group::1.sync.aligned.shared::cta.b32 [%0], %1;"
                     :: "r"(sm2u32(&s_tmem)), "r"(128u) : "memory");
        asm volatile("tcgen05.relinquish_alloc_permit.cta_group::1.sync.aligned;");
    }
    __syncthreads();
    const uint32_t tmem = s_tmem;
    const uint32_t mb0 = sm2u32(&s_mbar[0]);
    const float* Wbase = W2 + (size_t)e * FDIM * DIM + n0;

    const int NC = FDIM / KC;   // 64
    for (int c = 0; c < NC; c++) {
        const int st = c & 1;
        const uint32_t mb = mb0 + st * 8;
        if (c >= 2) mbar_wait(mb, ((c - 2) >> 1) & 1);
        const uint32_t A0 = sm + st * SMEM_STAGE;
        const uint32_t A1 = A0 + 16384, B0 = A0 + 32768, B1 = A0 + 49152;
        const int k0 = c * KC;
        #pragma unroll
        for (int j = 0; j < 4; j++) {                       // A: 128 x 32 from g_H
            int q = tid + j * 256;
            int r = q >> 3, k4 = q & 7;
            int rowg = base + min(m0 + r, count - 1);
            float4 v = *(const float4*)(g_H + (size_t)rowg * FDIM + k0 + k4 * 4);
            float hx, lx, hy, ly, hz, lz, hw, lw;
            split_tf32(v.x, hx, lx); split_tf32(v.y, hy, ly);
            split_tf32(v.z, hz, lz); split_tf32(v.w, hw, lw);
            uint32_t o = swoff(r, k4);
            sts128(A0 + o, hx, hy, hz, hw);
            sts128(A1 + o, lx, ly, lz, lw);
        }
        #pragma unroll
        for (int j = 0; j < 4; j++) {                       // B: 128 x 32 (W2 cols)
            int q = tid + j * 256;
            int n = q & 127, kq = q >> 7;
            const float* wp = Wbase + (size_t)(k0 + kq * 4) * DIM + n;
            float v0 = wp[0], v1 = wp[DIM], v2 = wp[2 * DIM], v3 = wp[3 * DIM];
            float h0, l0, h1, l1, h2, l2, h3, l3;
            split_tf32(v0, h0, l0); split_tf32(v1, h1, l1);
            split_tf32(v2, h2, l2); split_tf32(v3, h3, l3);
            uint32_t o = swoff(n, kq);
            sts128(B0 + o, h0, h1, h2, h3);
            sts128(B1 + o, l0, l1, l2, l3);
        }
        asm volatile("fence.proxy.async.shared::cta;" ::: "memory");
        __syncthreads();
        if (wid == 0 && elect1()) {
            uint64_t da0 = mk_desc(A0), da1 = mk_desc(A1);
            uint64_t db0 = mk_desc(B0), db1 = mk_desc(B1);
            #pragma unroll
            for (int s = 0; s < 4; s++) {
                mma_tf32(tmem, da0 + s * 2, db0 + s * 2, IDESC, (c | s) ? 1u : 0u);
                mma_tf32(tmem, da0 + s * 2, db1 + s * 2, IDESC, 1u);
                mma_tf32(tmem, da1 + s * 2, db0 + s * 2, IDESC, 1u);
            }
            tc_commit(mb);
        }
    }
    mbar_wait(mb0 + ((NC - 1) & 1) * 8, ((NC - 2) >> 1) & 1);
    asm volatile("tcgen05.fence::after_thread_sync;" ::: "memory");

    const int sp = wid & 3, half = wid >> 2;
    const int ml = sp * 32 + lane;
    const int mi = m0 + ml;
    const bool valid = mi < count;
    const int tok = toks[ml];
    const float gate = gts[ml];
    float* orow = out + (size_t)tok * DIM + n0;
    const float* bp = b2 + (size_t)e * DIM + n0;
    #pragma unroll
    for (int cb = 0; cb < 2; cb++) {
        const uint32_t c0 = half * 64 + cb * 32;
        uint32_t rg[32];
        LDTM32(rg, tmem + c0);
        asm volatile("tcgen05.wait::ld.sync.aligned;" ::: "memory");
        if (valid) {
            #pragma unroll
            for (int i = 0; i < 32; i++) {
                float y = __uint_as_float(rg[i]) + bp[c0 + i];
                atomicAdd(orow + c0 + i, gate * y);
            }
        }
    }
    asm volatile("tcgen05.fence::before_thread_sync;" ::: "memory");
    __syncthreads();
    if (tid == 0) { mbar_inval(mb0); mbar_inval(mb0 + 8); }
    if (wid == 0) {
        asm volatile("tcgen05.dealloc.cta_group::1.sync.aligned.b32 %0, %1;"
                     :: "r"(tmem), "r"(128u));
    }
#else
    // ---------- FFMA f32x2 fallback ----------
    float* As = (float*)dynraw;
    float* Bs = As + 16 * 132;
    __syncthreads();
    const int tx = tid & 15, ty = tid >> 4;
    unsigned long long acc[8][4];
    #pragma unroll
    for (int i = 0; i < 8; i++)
        #pragma unroll
        for (int j = 0; j < 4; j++) acc[i][j] = 0ull;
    const float* Wb = W2 + (size_t)e * FDIM * DIM + n0;
    for (int k0 = 0; k0 < FDIM; k0 += 16) {
        #pragma unroll
        for (int j = 0; j < 2; j++) {
            int q = tid + j * 256;
            int m = q >> 2, kq = q & 3;
            int rowg = base + min(m0 + m, count - 1);
            float4 v = *(const float4*)(g_H + (size_t)rowg * FDIM + k0 + kq * 4);
            As[(kq * 4 + 0) * 132 + m] = v.x; As[(kq * 4 + 1) * 132 + m] = v.y;
            As[(kq * 4 + 2) * 132 + m] = v.z; As[(kq * 4 + 3) * 132 + m] = v.w;
        }
        #pragma unroll
        for (int j = 0; j < 2; j++) {
            int q = tid + j * 256;
            int kk = q >> 5, nq = q & 31;
            float4 v = *(const float4*)(Wb + (size_t)(k0 + kk) * DIM + nq * 4);
            *(float4*)&Bs[kk * 132 + nq * 4] = v;
        }
        __syncthreads();
        #pragma unroll
        for (int k = 0; k < 16; k++) {
            float4 a0 = *(float4*)&As[k * 132 + ty * 4];
            float4 a1 = *(float4*)&As[k * 132 + 64 + ty * 4];
            float4 b0 = *(float4*)&Bs[k * 132 + tx * 4];
            float4 b1r = *(float4*)&Bs[k * 132 + 64 + tx * 4];
            unsigned long long bb[4];
            bb[0] = ((const unsigned long long*)&b0)[0];
            bb[1] = ((const unsigned long long*)&b0)[1];
            bb[2] = ((const unsigned long long*)&b1r)[0];
            bb[3] = ((const unsigned long long*)&b1r)[1];
            float av[8] = {a0.x, a0.y, a0.z, a0.w, a1.x, a1.y, a1.z, a1.w};
            #pragma unroll
            for (int i = 0; i < 8; i++) {
                unsigned long long aa = pack2(av[i]);
                #pragma unroll
                for (int jj = 0; jj < 4; jj++) acc[i][jj] = fma2(aa, bb[jj], acc[i][jj]);
            }
        }
        __syncthreads();
    }
    #pragma unroll
    for (int i = 0; i < 8; i++) {
        int mloc = (i < 4) ? (ty * 4 + i) : (64 + ty * 4 + (i - 4));
        int mi = m0 + mloc;
        if (mi >= count) continue;
        int tok = toks[mloc];
        float g = gts[mloc];
        float* orow = out + (size_t)tok * DIM + n0;
        #pragma unroll
        for (int jj = 0; jj < 4; jj++) {
            int nloc = (jj < 2) ? (tx * 4 + jj * 2) : (64 + tx * 4 + (jj - 2) * 2);
            float2 v = *(float2*)&acc[i][jj];
            atomicAdd(orow + nloc,     g * (v.x + b2[e * DIM + n0 + nloc]));
            atomicAdd(orow + nloc + 1, g * (v.y + b2[e * DIM + n0 + nloc + 1]));
        }
    }
#endif
}

// ==================== launch ====================
extern "C" void kernel_launch(void* const* d_in, const int* in_sizes, int n_in,
                              void* d_out, int out_size) {
    const float* x       = (const float*)d_in[0];
    const float* anchors = (const float*)d_in[1];
    const float* W1      = (const float*)d_in[2];
    const float* b1      = (const float*)d_in[3];
    const float* W2      = (const float*)d_in[4];
    const float* b2      = (const float*)d_in[5];
    float* out = (float*)d_out;

    static int attr_done = 0;
    if (!attr_done) {
        cudaFuncSetAttribute(k_gemm1, cudaFuncAttributeMaxDynamicSharedMemorySize, SMEM_DYN);
        cudaFuncSetAttribute(k_gemm2, cudaFuncAttributeMaxDynamicSharedMemorySize, SMEM_DYN);
        attr_done = 1;
    }

    const int OUT_END = T_TOK * DIM;
    const int AN_END  = OUT_END + NEXP * DIM;
    const int SC_END  = AN_END + T_TOK * NEXP;
    const int IX_END  = SC_END + T_TOK * 2;
    int write_an = (out_size >= AN_END) ? 1 : 0;
    int wflags = ((out_size >= SC_END) ? 1 : 0) | ((out_size >= IX_END) ? 2 : 0);

    k_zero<<<2048, 256>>>(out);
    k_anchors<<<1, 256>>>(anchors, out + OUT_END, write_an);
    k_route<<<512, 256>>>(x, out + AN_END, out + SC_END, wflags);
    k_offsets<<<1, 1>>>();
    dim3 g1(FDIM / TN, T_TOK / TM, NEXP);
    k_gemm1<<<g1, 256, SMEM_DYN>>>(x, W1, b1);
    dim3 g2(DIM / TN, T_TOK / TM, NEXP);
    k_gemm2<<<g2, 256, SMEM_DYN>>>(W2, b2, out);
}

// round 4
// speedup vs baseline: 2.4239x; 1.5547x over previous
#include <cuda_runtime.h>
#include <cstdint>

#define T_TOK 4096
#define DIM   512
#define FDIM  2048
#define NEXP  8
#define EPSV  1e-8f

#define TM   128
#define TN   128
#define KC   32

#if defined(__CUDA_ARCH__) && defined(__CUDA_ARCH_FEAT_SM103_ALL)
#define USE_TC 1
#else
#define USE_TC 0
#endif

#define SMEM_STAGE 32768            // B-hi (16KB) + B-lo (16KB)
#define SMEM_DYN   (2 * SMEM_STAGE + 1024)

// -------- scratch (static device globals; no runtime alloc) --------
__device__ float g_anchors_n[NEXP * DIM];
__device__ int   g_cnt[NEXP];
__device__ int   g_tok[NEXP][T_TOK];
__device__ float g_gate[NEXP][T_TOK];
__device__ float g_H[(2 * T_TOK) * FDIM];   // 8192 x 2048 fp32

// ==================== helpers ====================
__device__ __forceinline__ float gelu_f(float h) {
    return 0.5f * h * (1.f + erff(h * 0.7071067811865476f));
}
__device__ __forceinline__ unsigned long long pack2(float a) {
    unsigned long long r;
    asm("mov.b64 %0, {%1, %1};" : "=l"(r) : "f"(a));
    return r;
}
__device__ __forceinline__ unsigned long long fma2(unsigned long long a,
                                                   unsigned long long b,
                                                   unsigned long long c) {
    unsigned long long d;
    asm("fma.rn.f32x2 %0, %1, %2, %3;" : "=l"(d) : "l"(a), "l"(b), "l"(c));
    return d;
}

#if USE_TC
__device__ __forceinline__ uint32_t sm2u32(const void* p) {
    uint32_t a;
    asm("{ .reg .u64 t; cvta.to.shared.u64 t, %1; cvt.u32.u64 %0, t; }" : "=r"(a) : "l"(p));
    return a;
}
__device__ __forceinline__ bool elect1() {
    uint32_t r;
    asm volatile("{ .reg .pred p; elect.sync _|p, 0xFFFFFFFF; selp.b32 %0, 1, 0, p; }" : "=r"(r));
    return r != 0;
}
__device__ __forceinline__ void split_tf32(float f, float& hi, float& lo) {
    uint32_t u;
    asm("cvt.rna.tf32.f32 %0, %1;" : "=r"(u) : "f"(f));
    hi = __uint_as_float(u);
    float d = f - hi;
    uint32_t v;
    asm("cvt.rna.tf32.f32 %0, %1;" : "=r"(v) : "f"(d));
    lo = __uint_as_float(v);
}
__device__ __forceinline__ void sts128(uint32_t a, float x, float y, float z, float w) {
    asm volatile("st.shared.v4.b32 [%0], {%1,%2,%3,%4};"
                 :: "r"(a), "f"(x), "f"(y), "f"(z), "f"(w) : "memory");
}
__device__ __forceinline__ void mbar_init(uint32_t a, uint32_t c) {
    asm volatile("mbarrier.init.shared.b64 [%0], %1;" :: "r"(a), "r"(c) : "memory");
}
__device__ __forceinline__ void mbar_inval(uint32_t a) {
    asm volatile("mbarrier.inval.shared.b64 [%0];" :: "r"(a) : "memory");
}
__device__ __forceinline__ void mbar_wait(uint32_t a, uint32_t ph) {
    uint32_t done;
    asm volatile("{\n\t.reg .pred p;\n\t"
                 "mbarrier.try_wait.parity.acquire.cta.shared::cta.b64 p, [%1], %2;\n\t"
                 "selp.b32 %0, 1, 0, p;\n\t}"
                 : "=r"(done) : "r"(a), "r"(ph) : "memory");
    if (!done) {
        asm volatile("{\n\t.reg .pred P1;\n\t"
                     "LW%=:\n\t"
                     "mbarrier.try_wait.parity.acquire.cta.shared::cta.b64 P1, [%0], %1, 0x989680;\n\t"
                     "@P1 bra.uni LD%=;\n\t"
                     "bra.uni LW%=;\n\t"
                     "LD%=:\n\t}"
                     :: "r"(a), "r"(ph) : "memory");
    }
}
__device__ __forceinline__ void tc_commit(uint32_t mb) {
    asm volatile("tcgen05.commit.cta_group::1.mbarrier::arrive::one.shared::cluster.b64 [%0];"
                 :: "r"(mb) : "memory");
}
// TS-mode: A from TMEM, B from SMEM desc
__device__ __forceinline__ void mma_tf32_ts(uint32_t d, uint32_t a, uint64_t b,
                                            uint32_t idesc, uint32_t en) {
    asm volatile("{\n\t.reg .pred p;\n\tsetp.ne.u32 p, %4, 0;\n\t"
                 "tcgen05.mma.cta_group::1.kind::tf32 [%0], [%1], %2, %3, {%5,%5,%5,%5}, p;\n\t}"
                 :: "r"(d), "r"(a), "l"(b), "r"(idesc), "r"(en), "r"(0u) : "memory");
}
#define STTM16(ta, r) \
    asm volatile( \
        "tcgen05.st.sync.aligned.32x32b.x16.b32 [%0], " \
        "{%1, %2, %3, %4, %5, %6, %7, %8, " \
        " %9, %10, %11, %12, %13, %14, %15, %16};" \
        :: "r"(ta), \
           "f"((r)[0]),  "f"((r)[1]),  "f"((r)[2]),  "f"((r)[3]), \
           "f"((r)[4]),  "f"((r)[5]),  "f"((r)[6]),  "f"((r)[7]), \
           "f"((r)[8]),  "f"((r)[9]),  "f"((r)[10]), "f"((r)[11]), \
           "f"((r)[12]), "f"((r)[13]), "f"((r)[14]), "f"((r)[15]) \
        : "memory")
#define LDTM32(r, ta) \
    asm volatile( \
        "tcgen05.ld.sync.aligned.32x32b.x32.b32 " \
        "{%0, %1, %2, %3, %4, %5, %6, %7, " \
        " %8, %9, %10, %11, %12, %13, %14, %15, " \
        " %16, %17, %18, %19, %20, %21, %22, %23, " \
        " %24, %25, %26, %27, %28, %29, %30, %31}, [%32];" \
        : "=r"((r)[0]),  "=r"((r)[1]),  "=r"((r)[2]),  "=r"((r)[3]), \
          "=r"((r)[4]),  "=r"((r)[5]),  "=r"((r)[6]),  "=r"((r)[7]), \
          "=r"((r)[8]),  "=r"((r)[9]),  "=r"((r)[10]), "=r"((r)[11]), \
          "=r"((r)[12]), "=r"((r)[13]), "=r"((r)[14]), "=r"((r)[15]), \
          "=r"((r)[16]), "=r"((r)[17]), "=r"((r)[18]), "=r"((r)[19]), \
          "=r"((r)[20]), "=r"((r)[21]), "=r"((r)[22]), "=r"((r)[23]), \
          "=r"((r)[24]), "=r"((r)[25]), "=r"((r)[26]), "=r"((r)[27]), \
          "=r"((r)[28]), "=r"((r)[29]), "=r"((r)[30]), "=r"((r)[31]) \
        : "r"(ta))

__device__ __forceinline__ uint64_t mk_desc(uint32_t addr) {
    // SW128, version=1 (Blackwell), SBO=64, LBO=1
    return ((uint64_t)2 << 61) | ((uint64_t)1 << 46) | ((uint64_t)64 << 32) |
           ((uint64_t)1 << 16) | ((uint64_t)(addr >> 4) & 0x3FFF);
}
__device__ __forceinline__ uint32_t swoff(int r, int c16) {
    return (uint32_t)(((r >> 3) << 10) + ((r & 7) << 7) + (((c16 ^ (r & 7)) & 7) << 4));
}
// idesc: c=F32(1), a=TF32(2), b=TF32(2), N=128, M=128
#define IDESC ((1u << 4) | (2u << 7) | (2u << 10) | ((TN / 8) << 17) | ((TM / 16) << 24))
// TMEM columns: D at 0..127, A stage st: hi at 128+st*64, lo at +32
#define TMEM_NCOLS 256
#define TM_D 0
#define TM_A(st) (128 + (st) * 64)
#endif  // USE_TC

// ==================== small kernels ====================
__global__ void k_anchors(const float* __restrict__ A, float* __restrict__ an_out,
                          int write_an) {
    int w = threadIdx.x >> 5, lane = threadIdx.x & 31;
    if (threadIdx.x < NEXP) g_cnt[threadIdx.x] = 0;
    float ss = 0.f;
    for (int d = lane; d < DIM; d += 32) { float v = A[w * DIM + d]; ss += v * v; }
    #pragma unroll
    for (int o = 16; o; o >>= 1) ss += __shfl_xor_sync(0xffffffffu, ss, o);
    float inv = 1.f / fmaxf(sqrtf(ss), EPSV);
    for (int d = lane; d < DIM; d += 32) {
        float v = A[w * DIM + d] * inv;
        g_anchors_n[w * DIM + d] = v;
        if (write_an) an_out[w * DIM + d] = v;
    }
}

__global__ void k_route(const float* __restrict__ x, float* __restrict__ out,
                        float* __restrict__ scores_out,
                        float* __restrict__ idx_out, int wflags) {
    // zero MoE output region (each thread 4 float4 = 16 floats)
    {
        int t = blockIdx.x * blockDim.x + threadIdx.x;   // 131072 threads
        float4* o4 = (float4*)out;
        #pragma unroll
        for (int j = 0; j < 4; j++)
            o4[t * 4 + j] = make_float4(0.f, 0.f, 0.f, 0.f);
    }
    int wid = (blockIdx.x * blockDim.x + threadIdx.x) >> 5;
    int lane = threadIdx.x & 31;
    if (wid >= T_TOK) return;
    const float* xr = x + (size_t)wid * DIM;
    float xx = 0.f;
    float dt[NEXP];
    #pragma unroll
    for (int e = 0; e < NEXP; e++) dt[e] = 0.f;
    for (int d = lane; d < DIM; d += 32) {
        float xv = xr[d];
        xx += xv * xv;
        #pragma unroll
        for (int e = 0; e < NEXP; e++) dt[e] += xv * g_anchors_n[e * DIM + d];
    }
    #pragma unroll
    for (int o = 16; o; o >>= 1) {
        xx += __shfl_xor_sync(0xffffffffu, xx, o);
        #pragma unroll
        for (int e = 0; e < NEXP; e++) dt[e] += __shfl_xor_sync(0xffffffffu, dt[e], o);
    }
    if (lane == 0) {
        float inv = 1.f / fmaxf(sqrtf(xx), EPSV);
        float s[NEXP];
        #pragma unroll
        for (int e = 0; e < NEXP; e++) s[e] = dt[e] * inv;
        int i1 = 0; float v1 = s[0];
        #pragma unroll
        for (int e = 1; e < NEXP; e++) if (s[e] > v1) { v1 = s[e]; i1 = e; }
        int i2 = -1; float v2 = -1e30f;
        #pragma unroll
        for (int e = 0; e < NEXP; e++) if (e != i1 && s[e] > v2) { v2 = s[e]; i2 = e; }
        float e2 = expf(v2 - v1);
        float denom = 1.f / (1.f + e2);
        float g1 = denom, g2 = e2 * denom;
        int s1 = atomicAdd(&g_cnt[i1], 1);
        g_tok[i1][s1] = wid; g_gate[i1][s1] = g1;
        int s2 = atomicAdd(&g_cnt[i2], 1);
        g_tok[i2][s2] = wid; g_gate[i2][s2] = g2;
        if (wflags & 1) {
            #pragma unroll
            for (int e = 0; e < NEXP; e++) scores_out[wid * NEXP + e] = s[e];
        }
        if (wflags & 2) {
            idx_out[wid * 2 + 0] = (float)i1;
            idx_out[wid * 2 + 1] = (float)i2;
        }
    }
}

// ==================== GEMM1: H = gelu(Xg @ W1[e] + b1[e]) ====================
__global__ __launch_bounds__(256, 2)
void k_gemm1(const float* __restrict__ x, const float* __restrict__ W1,
             const float* __restrict__ b1) {
    const int e = blockIdx.z;
    const int count = g_cnt[e];
    const int m0 = blockIdx.y * TM;
    if (m0 >= count) return;
    const int n0 = blockIdx.x * TN;
    const int tid = threadIdx.x;
    const int wid = tid >> 5, lane = tid & 31;
    extern __shared__ char dynraw[];
    __shared__ int toks[TM];
    __shared__ int s_base;
    if (tid < TM) toks[tid] = g_tok[e][min(m0 + tid, count - 1)];
    if (tid == 0) {
        int b = 0;
        for (int i = 0; i < e; i++) b += g_cnt[i];
        s_base = b;
    }

#if USE_TC
    __shared__ __align__(8) unsigned long long s_mbar[2];
    __shared__ uint32_t s_tmem;
    const uint32_t sm = (sm2u32(dynraw) + 1023u) & ~1023u;
    if (tid == 0) { mbar_init(sm2u32(&s_mbar[0]), 1); mbar_init(sm2u32(&s_mbar[1]), 1); }
    if (wid == 0) {
        asm volatile("tcgen05.alloc.cta_group::1.sync.aligned.shared::cta.b32 [%0], %1;"
                     :: "r"(sm2u32(&s_tmem)), "r"((uint32_t)TMEM_NCOLS) : "memory");
        asm volatile("tcgen05.relinquish_alloc_permit.cta_group::1.sync.aligned;");
    }
    __syncthreads();
    const uint32_t tmem = s_tmem;
    const int base = s_base;
    const uint32_t mb0 = sm2u32(&s_mbar[0]);
    const float* Wbase = W1 + (size_t)e * DIM * FDIM + n0;

    const int NC = DIM / KC;   // 16
    for (int c = 0; c < NC; c++) {
        const int st = c & 1;
        const uint32_t mb = mb0 + st * 8;
        if (c >= 2) {
            mbar_wait(mb, ((c - 2) >> 1) & 1);
            asm volatile("tcgen05.fence::after_thread_sync;" ::: "memory");
        }
        const uint32_t B0 = sm + st * SMEM_STAGE;
        const uint32_t B1 = B0 + 16384;
        const int k0 = c * KC;
        if (tid < 128) {
            // A producer: row = tid, 32 k-values -> hi/lo -> TMEM
            const float* xr = x + (size_t)toks[tid] * DIM + k0;
            const uint32_t woff = ((uint32_t)(tid >> 5)) << 21;
            #pragma unroll
            for (int h = 0; h < 2; h++) {
                float hi[16], lo[16];
                #pragma unroll
                for (int q = 0; q < 4; q++) {
                    float4 v = *(const float4*)(xr + h * 16 + q * 4);
                    split_tf32(v.x, hi[q * 4 + 0], lo[q * 4 + 0]);
                    split_tf32(v.y, hi[q * 4 + 1], lo[q * 4 + 1]);
                    split_tf32(v.z, hi[q * 4 + 2], lo[q * 4 + 2]);
                    split_tf32(v.w, hi[q * 4 + 3], lo[q * 4 + 3]);
                }
                STTM16(tmem + TM_A(st) + h * 16 + woff, hi);
                STTM16(tmem + TM_A(st) + 32 + h * 16 + woff, lo);
            }
            asm volatile("tcgen05.wait::st.sync.aligned;" ::: "memory");
            asm volatile("tcgen05.fence::before_thread_sync;" ::: "memory");
        } else {
            // B producer: n = tid-128, 32 k-values -> hi/lo -> SMEM SW128
            const int n = tid - 128;
            const float* wp = Wbase + (size_t)k0 * FDIM + n;
            #pragma unroll
            for (int kq = 0; kq < 8; kq++) {
                float v0 = wp[(kq * 4 + 0) * FDIM];
                float v1 = wp[(kq * 4 + 1) * FDIM];
                float v2 = wp[(kq * 4 + 2) * FDIM];
                float v3 = wp[(kq * 4 + 3) * FDIM];
                float h0, l0, h1, l1, h2, l2, h3, l3;
                split_tf32(v0, h0, l0); split_tf32(v1, h1, l1);
                split_tf32(v2, h2, l2); split_tf32(v3, h3, l3);
                uint32_t o = swoff(n, kq);
                sts128(B0 + o, h0, h1, h2, h3);
                sts128(B1 + o, l0, l1, l2, l3);
            }
            asm volatile("fence.proxy.async.shared::cta;" ::: "memory");
        }
        __syncthreads();
        if (wid == 0 && elect1()) {
            asm volatile("tcgen05.fence::after_thread_sync;" ::: "memory");
            uint64_t dbh = mk_desc(B0), dbl = mk_desc(B1);
            const uint32_t ah = tmem + TM_A(st), al = ah + 32;
            #pragma unroll
            for (int s = 0; s < 4; s++) {
                mma_tf32_ts(tmem + TM_D, ah + s * 8, dbh + s * 2, IDESC, (c | s) ? 1u : 0u);
                mma_tf32_ts(tmem + TM_D, ah + s * 8, dbl + s * 2, IDESC, 1u);
                mma_tf32_ts(tmem + TM_D, al + s * 8, dbh + s * 2, IDESC, 1u);
            }
            tc_commit(mb);
        }
    }
    mbar_wait(mb0 + ((NC - 1) & 1) * 8, ((NC - 2) >> 1) & 1);
    asm volatile("tcgen05.fence::after_thread_sync;" ::: "memory");

    const int sp = wid & 3, half = wid >> 2;
    const int mi = m0 + sp * 32 + lane;
    const bool valid = mi < count;
    float* Hrow = g_H + (size_t)(base + (valid ? mi : 0)) * FDIM + n0;
    const float* bp = b1 + (size_t)e * FDIM + n0;
    #pragma unroll
    for (int cb = 0; cb < 2; cb++) {
        const uint32_t c0 = half * 64 + cb * 32;
        uint32_t rg[32];
        LDTM32(rg, tmem + TM_D + c0);
        asm volatile("tcgen05.wait::ld.sync.aligned;" ::: "memory");
        if (valid) {
            #pragma unroll
            for (int i = 0; i < 32; i += 4) {
                float4 o;
                o.x = gelu_f(__uint_as_float(rg[i + 0]) + bp[c0 + i + 0]);
                o.y = gelu_f(__uint_as_float(rg[i + 1]) + bp[c0 + i + 1]);
                o.z = gelu_f(__uint_as_float(rg[i + 2]) + bp[c0 + i + 2]);
                o.w = gelu_f(__uint_as_float(rg[i + 3]) + bp[c0 + i + 3]);
                *(float4*)(Hrow + c0 + i) = o;
            }
        }
    }
    asm volatile("tcgen05.fence::before_thread_sync;" ::: "memory");
    __syncthreads();
    if (tid == 0) { mbar_inval(mb0); mbar_inval(mb0 + 8); }
    if (wid == 0) {
        asm volatile("tcgen05.dealloc.cta_group::1.sync.aligned.b32 %0, %1;"
                     :: "r"(tmem), "r"((uint32_t)TMEM_NCOLS));
    }
#else
    // ---------- FFMA f32x2 fallback ----------
    float* As = (float*)dynraw;               // [16][132]
    float* Bs = As + 16 * 132;                // [16][132]
    __syncthreads();
    const int base = s_base;
    const int tx = tid & 15, ty = tid >> 4;
    unsigned long long acc[8][4];
    #pragma unroll
    for (int i = 0; i < 8; i++)
        #pragma unroll
        for (int j = 0; j < 4; j++) acc[i][j] = 0ull;
    const float* Wb = W1 + (size_t)e * DIM * FDIM + n0;
    for (int k0 = 0; k0 < DIM; k0 += 16) {
        #pragma unroll
        for (int j = 0; j < 2; j++) {
            int q = tid + j * 256;
            int m = q >> 2, kq = q & 3;
            float4 v = *(const float4*)(x + (size_t)toks[m] * DIM + k0 + kq * 4);
            As[(kq * 4 + 0) * 132 + m] = v.x; As[(kq * 4 + 1) * 132 + m] = v.y;
            As[(kq * 4 + 2) * 132 + m] = v.z; As[(kq * 4 + 3) * 132 + m] = v.w;
        }
        #pragma unroll
        for (int j = 0; j < 2; j++) {
            int q = tid + j * 256;
            int kk = q >> 5, nq = q & 31;
            float4 v = *(const float4*)(Wb + (size_t)(k0 + kk) * FDIM + nq * 4);
            *(float4*)&Bs[kk * 132 + nq * 4] = v;
        }
        __syncthreads();
        #pragma unroll
        for (int k = 0; k < 16; k++) {
            float4 a0 = *(float4*)&As[k * 132 + ty * 4];
            float4 a1 = *(float4*)&As[k * 132 + 64 + ty * 4];
            float4 b0 = *(float4*)&Bs[k * 132 + tx * 4];
            float4 b1r = *(float4*)&Bs[k * 132 + 64 + tx * 4];
            unsigned long long bb[4];
            bb[0] = ((const unsigned long long*)&b0)[0];
            bb[1] = ((const unsigned long long*)&b0)[1];
            bb[2] = ((const unsigned long long*)&b1r)[0];
            bb[3] = ((const unsigned long long*)&b1r)[1];
            float av[8] = {a0.x, a0.y, a0.z, a0.w, a1.x, a1.y, a1.z, a1.w};
            #pragma unroll
            for (int i = 0; i < 8; i++) {
                unsigned long long aa = pack2(av[i]);
                #pragma unroll
                for (int jj = 0; jj < 4; jj++) acc[i][jj] = fma2(aa, bb[jj], acc[i][jj]);
            }
        }
        __syncthreads();
    }
    #pragma unroll
    for (int i = 0; i < 8; i++) {
        int mloc = (i < 4) ? (ty * 4 + i) : (64 + ty * 4 + (i - 4));
        int mi = m0 + mloc;
        if (mi >= count) continue;
        float* Hrow = g_H + (size_t)(base + mi) * FDIM + n0;
        #pragma unroll
        for (int jj = 0; jj < 4; jj++) {
            int nloc = (jj < 2) ? (tx * 4 + jj * 2) : (64 + tx * 4 + (jj - 2) * 2);
            float2 v = *(float2*)&acc[i][jj];
            float h0 = gelu_f(v.x + b1[e * FDIM + n0 + nloc]);
            float h1 = gelu_f(v.y + b1[e * FDIM + n0 + nloc + 1]);
            *(float2*)(Hrow + nloc) = make_float2(h0, h1);
        }
    }
#endif
}

// ==================== GEMM2: out += gate * (H @ W2[e] + b2[e]) ====================
__global__ __launch_bounds__(256, 2)
void k_gemm2(const float* __restrict__ W2, const float* __restrict__ b2,
             float* __restrict__ out) {
    const int e = blockIdx.z;
    const int count = g_cnt[e];
    const int m0 = blockIdx.y * TM;
    if (m0 >= count) return;
    const int n0 = blockIdx.x * TN;
    const int tid = threadIdx.x;
    const int wid = tid >> 5, lane = tid & 31;
    extern __shared__ char dynraw[];
    __shared__ int   toks[TM];
    __shared__ float gts[TM];
    __shared__ int s_base;
    if (tid < TM) {
        int mi = min(m0 + tid, count - 1);
        toks[tid] = g_tok[e][mi];
        gts[tid]  = g_gate[e][mi];
    }
    if (tid == 0) {
        int b = 0;
        for (int i = 0; i < e; i++) b += g_cnt[i];
        s_base = b;
    }

#if USE_TC
    __shared__ __align__(8) unsigned long long s_mbar[2];
    __shared__ uint32_t s_tmem;
    const uint32_t sm = (sm2u32(dynraw) + 1023u) & ~1023u;
    if (tid == 0) { mbar_init(sm2u32(&s_mbar[0]), 1); mbar_init(sm2u32(&s_mbar[1]), 1); }
    if (wid == 0) {
        asm volatile("tcgen05.alloc.cta_group::1.sync.aligned.shared::cta.b32 [%0], %1;"
                     :: "r"(sm2u32(&s_tmem)), "r"((uint32_t)TMEM_NCOLS) : "memory");
        asm volatile("tcgen05.relinquish_alloc_permit.cta_group::1.sync.aligned;");
    }
    __syncthreads();
    const uint32_t tmem = s_tmem;
    const int base = s_base;
    const uint32_t mb0 = sm2u32(&s_mbar[0]);
    const float* Wbase = W2 + (size_t)e * FDIM * DIM + n0;

    const int NC = FDIM / KC;   // 64
    for (int c = 0; c < NC; c++) {
        const int st = c & 1;
        const uint32_t mb = mb0 + st * 8;
        if (c >= 2) {
            mbar_wait(mb, ((c - 2) >> 1) & 1);
            asm volatile("tcgen05.fence::after_thread_sync;" ::: "memory");
        }
        const uint32_t B0 = sm + st * SMEM_STAGE;
        const uint32_t B1 = B0 + 16384;
        const int k0 = c * KC;
        if (tid < 128) {
            const int rowg = base + min(m0 + tid, count - 1);
            const float* hr = g_H + (size_t)rowg * FDIM + k0;
            const uint32_t woff = ((uint32_t)(tid >> 5)) << 21;
            #pragma unroll
            for (int h = 0; h < 2; h++) {
                float hi[16], lo[16];
                #pragma unroll
                for (int q = 0; q < 4; q++) {
                    float4 v = *(const float4*)(hr + h * 16 + q * 4);
                    split_tf32(v.x, hi[q * 4 + 0], lo[q * 4 + 0]);
                    split_tf32(v.y, hi[q * 4 + 1], lo[q * 4 + 1]);
                    split_tf32(v.z, hi[q * 4 + 2], lo[q * 4 + 2]);
                    split_tf32(v.w, hi[q * 4 + 3], lo[q * 4 + 3]);
                }
                STTM16(tmem + TM_A(st) + h * 16 + woff, hi);
                STTM16(tmem + TM_A(st) + 32 + h * 16 + woff, lo);
            }
            asm volatile("tcgen05.wait::st.sync.aligned;" ::: "memory");
            asm volatile("tcgen05.fence::before_thread_sync;" ::: "memory");
        } else {
            const int n = tid - 128;
            const float* wp = Wbase + (size_t)k0 * DIM + n;
            #pragma unroll
            for (int kq = 0; kq < 8; kq++) {
                float v0 = wp[(kq * 4 + 0) * DIM];
                float v1 = wp[(kq * 4 + 1) * DIM];
                float v2 = wp[(kq * 4 + 2) * DIM];
                float v3 = wp[(kq * 4 + 3) * DIM];
                float h0, l0, h1, l1, h2, l2, h3, l3;
                split_tf32(v0, h0, l0); split_tf32(v1, h1, l1);
                split_tf32(v2, h2, l2); split_tf32(v3, h3, l3);
                uint32_t o = swoff(n, kq);
                sts128(B0 + o, h0, h1, h2, h3);
                sts128(B1 + o, l0, l1, l2, l3);
            }
            asm volatile("fence.proxy.async.shared::cta;" ::: "memory");
        }
        __syncthreads();
        if (wid == 0 && elect1()) {
            asm volatile("tcgen05.fence::after_thread_sync;" ::: "memory");
            uint64_t dbh = mk_desc(B0), dbl = mk_desc(B1);
            const uint32_t ah = tmem + TM_A(st), al = ah + 32;
            #pragma unroll
            for (int s = 0; s < 4; s++) {
                mma_tf32_ts(tmem + TM_D, ah + s * 8, dbh + s * 2, IDESC, (c | s) ? 1u : 0u);
                mma_tf32_ts(tmem + TM_D, ah + s * 8, dbl + s * 2, IDESC, 1u);
                mma_tf32_ts(tmem + TM_D, al + s * 8, dbh + s * 2, IDESC, 1u);
            }
            tc_commit(mb);
        }
    }
    mbar_wait(mb0 + ((NC - 1) & 1) * 8, ((NC - 2) >> 1) & 1);
    asm volatile("tcgen05.fence::after_thread_sync;" ::: "memory");

    const int sp = wid & 3, half = wid >> 2;
    const int ml = sp * 32 + lane;
    const int mi = m0 + ml;
    const bool valid = mi < count;
    const int tok = toks[ml];
    const float gate = gts[ml];
    float* orow = out + (size_t)tok * DIM + n0;
    const float* bp = b2 + (size_t)e * DIM + n0;
    #pragma unroll
    for (int cb = 0; cb < 2; cb++) {
        const uint32_t c0 = half * 64 + cb * 32;
        uint32_t rg[32];
        LDTM32(rg, tmem + TM_D + c0);
        asm volatile("tcgen05.wait::ld.sync.aligned;" ::: "memory");
        if (valid) {
            #pragma unroll
            for (int i = 0; i < 32; i++) {
                float y = __uint_as_float(rg[i]) + bp[c0 + i];
                atomicAdd(orow + c0 + i, gate * y);
            }
        }
    }
    asm volatile("tcgen05.fence::before_thread_sync;" ::: "memory");
    __syncthreads();
    if (tid == 0) { mbar_inval(mb0); mbar_inval(mb0 + 8); }
    if (wid == 0) {
        asm volatile("tcgen05.dealloc.cta_group::1.sync.aligned.b32 %0, %1;"
                     :: "r"(tmem), "r"((uint32_t)TMEM_NCOLS));
    }
#else
    // ---------- FFMA f32x2 fallback ----------
    float* As = (float*)dynraw;
    float* Bs = As + 16 * 132;
    __syncthreads();
    const int base = s_base;
    const int tx = tid & 15, ty = tid >> 4;
    unsigned long long acc[8][4];
    #pragma unroll
    for (int i = 0; i < 8; i++)
        #pragma unroll
        for (int j = 0; j < 4; j++) acc[i][j] = 0ull;
    const float* Wb = W2 + (size_t)e * FDIM * DIM + n0;
    for (int k0 = 0; k0 < FDIM; k0 += 16) {
        #pragma unroll
        for (int j = 0; j < 2; j++) {
            int q = tid + j * 256;
            int m = q >> 2, kq = q & 3;
            int rowg = base + min(m0 + m, count - 1);
            float4 v = *(const float4*)(g_H + (size_t)rowg * FDIM + k0 + kq * 4);
            As[(kq * 4 + 0) * 132 + m] = v.x; As[(kq * 4 + 1) * 132 + m] = v.y;
            As[(kq * 4 + 2) * 132 + m] = v.z; As[(kq * 4 + 3) * 132 + m] = v.w;
        }
        #pragma unroll
        for (int j = 0; j < 2; j++) {
            int q = tid + j * 256;
            int kk = q >> 5, nq = q & 31;
            float4 v = *(const float4*)(Wb + (size_t)(k0 + kk) * DIM + nq * 4);
            *(float4*)&Bs[kk * 132 + nq * 4] = v;
        }
        __syncthreads();
        #pragma unroll
        for (int k = 0; k < 16; k++) {
            float4 a0 = *(float4*)&As[k * 132 + ty * 4];
            float4 a1 = *(float4*)&As[k * 132 + 64 + ty * 4];
            float4 b0 = *(float4*)&Bs[k * 132 + tx * 4];
            float4 b1r = *(float4*)&Bs[k * 132 + 64 + tx * 4];
            unsigned long long bb[4];
            bb[0] = ((const unsigned long long*)&b0)[0];
            bb[1] = ((const unsigned long long*)&b0)[1];
            bb[2] = ((const unsigned long long*)&b1r)[0];
            bb[3] = ((const unsigned long long*)&b1r)[1];
            float av[8] = {a0.x, a0.y, a0.z, a0.w, a1.x, a1.y, a1.z, a1.w};
            #pragma unroll
            for (int i = 0; i < 8; i++) {
                unsigned long long aa = pack2(av[i]);
                #pragma unroll
                for (int jj = 0; jj < 4; jj++) acc[i][jj] = fma2(aa, bb[jj], acc[i][jj]);
            }
        }
        __syncthreads();
    }
    #pragma unroll
    for (int i = 0; i < 8; i++) {
        int mloc = (i < 4) ? (ty * 4 + i) : (64 + ty * 4 + (i - 4));
        int mi = m0 + mloc;
        if (mi >= count) continue;
        int tok = toks[mloc];
        float g = gts[mloc];
        float* orow = out + (size_t)tok * DIM + n0;
        #pragma unroll
        for (int jj = 0; jj < 4; jj++) {
            int nloc = (jj < 2) ? (tx * 4 + jj * 2) : (64 + tx * 4 + (jj - 2) * 2);
            float2 v = *(float2*)&acc[i][jj];
            atomicAdd(orow + nloc,     g * (v.x + b2[e * DIM + n0 + nloc]));
            atomicAdd(orow + nloc + 1, g * (v.y + b2[e * DIM + n0 + nloc + 1]));
        }
    }
#endif
}

// ==================== launch ====================
extern "C" void kernel_launch(void* const* d_in, const int* in_sizes, int n_in,
                              void* d_out, int out_size) {
    const float* x       = (const float*)d_in[0];
    const float* anchors = (const float*)d_in[1];
    const float* W1      = (const float*)d_in[2];
    const float* b1      = (const float*)d_in[3];
    const float* W2      = (const float*)d_in[4];
    const float* b2      = (const float*)d_in[5];
    float* out = (float*)d_out;

    static int attr_done = 0;
    if (!attr_done) {
        cudaFuncSetAttribute(k_gemm1, cudaFuncAttributeMaxDynamicSharedMemorySize, SMEM_DYN);
        cudaFuncSetAttribute(k_gemm2, cudaFuncAttributeMaxDynamicSharedMemorySize, SMEM_DYN);
        attr_done = 1;
    }

    const int OUT_END = T_TOK * DIM;
    const int AN_END  = OUT_END + NEXP * DIM;
    const int SC_END  = AN_END + T_TOK * NEXP;
    const int IX_END  = SC_END + T_TOK * 2;
    int write_an = (out_size >= AN_END) ? 1 : 0;
    int wflags = ((out_size >= SC_END) ? 1 : 0) | ((out_size >= IX_END) ? 2 : 0);

    k_anchors<<<1, 256>>>(anchors, out + OUT_END, write_an);
    k_route<<<512, 256>>>(x, out, out + AN_END, out + SC_END, wflags);
    dim3 g1(FDIM / TN, T_TOK / TM, NEXP);
    k_gemm1<<<g1, 256, SMEM_DYN>>>(x, W1, b1);
    dim3 g2(DIM / TN, T_TOK / TM, NEXP);
    k_gemm2<<<g2, 256, SMEM_DYN>>>(W2, b2, out);
}

// round 5
// speedup vs baseline: 2.8383x; 1.1710x over previous
#include <cuda_runtime.h>
#include <cstdint>

#define T_TOK 4096
#define DIM   512
#define FDIM  2048
#define NEXP  8
#define EPSV  1e-8f

#define TM   128
#define TN   128
#define KC   64

#if defined(__CUDA_ARCH__) && defined(__CUDA_ARCH_FEAT_SM103_ALL)
#define USE_TC 1
#else
#define USE_TC 0
#endif

#define SMEM_STAGE 32768            // 2 x 16KB blocks (each: 128 rows x [64B hi | 64B lo])
#define SMEM_DYN   (2 * SMEM_STAGE + 1024)

// -------- scratch (static device globals; no runtime alloc) --------
__device__ float g_anchors_n[NEXP * DIM];
__device__ int   g_cnt[NEXP];
__device__ int   g_tok[NEXP][T_TOK];
__device__ float g_gate[NEXP][T_TOK];
__device__ float g_H[(2 * T_TOK) * FDIM];   // 8192 x 2048 fp32

// ==================== helpers ====================
__device__ __forceinline__ float gelu_f(float h) {
    return 0.5f * h * (1.f + erff(h * 0.7071067811865476f));
}
__device__ __forceinline__ unsigned long long pack2(float a) {
    unsigned long long r;
    asm("mov.b64 %0, {%1, %1};" : "=l"(r) : "f"(a));
    return r;
}
__device__ __forceinline__ unsigned long long fma2(unsigned long long a,
                                                   unsigned long long b,
                                                   unsigned long long c) {
    unsigned long long d;
    asm("fma.rn.f32x2 %0, %1, %2, %3;" : "=l"(d) : "l"(a), "l"(b), "l"(c));
    return d;
}

#if USE_TC
__device__ __forceinline__ uint32_t sm2u32(const void* p) {
    uint32_t a;
    asm("{ .reg .u64 t; cvta.to.shared.u64 t, %1; cvt.u32.u64 %0, t; }" : "=r"(a) : "l"(p));
    return a;
}
__device__ __forceinline__ bool elect1() {
    uint32_t r;
    asm volatile("{ .reg .pred p; elect.sync _|p, 0xFFFFFFFF; selp.b32 %0, 1, 0, p; }" : "=r"(r));
    return r != 0;
}
// split pair of floats into packed bf16x2 hi + lo (lo = residual)
__device__ __forceinline__ void split2_bf16(float v0, float v1, uint32_t& hw, uint32_t& lw) {
    asm("cvt.rn.satfinite.bf16x2.f32 %0, %1, %2;" : "=r"(hw) : "f"(v1), "f"(v0));
    float h0 = __uint_as_float(hw << 16);
    float h1 = __uint_as_float(hw & 0xffff0000u);
    asm("cvt.rn.satfinite.bf16x2.f32 %0, %1, %2;" : "=r"(lw) : "f"(v1 - h1), "f"(v0 - h0));
}
__device__ __forceinline__ void sts128u(uint32_t a, const uint32_t* w) {
    asm volatile("st.shared.v4.b32 [%0], {%1,%2,%3,%4};"
                 :: "r"(a), "r"(w[0]), "r"(w[1]), "r"(w[2]), "r"(w[3]) : "memory");
}
__device__ __forceinline__ void mbar_init(uint32_t a, uint32_t c) {
    asm volatile("mbarrier.init.shared.b64 [%0], %1;" :: "r"(a), "r"(c) : "memory");
}
__device__ __forceinline__ void mbar_inval(uint32_t a) {
    asm volatile("mbarrier.inval.shared.b64 [%0];" :: "r"(a) : "memory");
}
__device__ __forceinline__ void mbar_wait(uint32_t a, uint32_t ph) {
    uint32_t done;
    asm volatile("{\n\t.reg .pred p;\n\t"
                 "mbarrier.try_wait.parity.acquire.cta.shared::cta.b64 p, [%1], %2;\n\t"
                 "selp.b32 %0, 1, 0, p;\n\t}"
                 : "=r"(done) : "r"(a), "r"(ph) : "memory");
    if (!done) {
        asm volatile("{\n\t.reg .pred P1;\n\t"
                     "LW%=:\n\t"
                     "mbarrier.try_wait.parity.acquire.cta.shared::cta.b64 P1, [%0], %1, 0x989680;\n\t"
                     "@P1 bra.uni LD%=;\n\t"
                     "bra.uni LW%=;\n\t"
                     "LD%=:\n\t}"
                     :: "r"(a), "r"(ph) : "memory");
    }
}
__device__ __forceinline__ void tc_commit(uint32_t mb) {
    asm volatile("tcgen05.commit.cta_group::1.mbarrier::arrive::one.shared::cluster.b64 [%0];"
                 :: "r"(mb) : "memory");
}
// TS-mode bf16: A from TMEM, B from SMEM desc
__device__ __forceinline__ void mma_f16_ts(uint32_t d, uint32_t a, uint64_t b,
                                           uint32_t idesc, uint32_t en) {
    asm volatile("{\n\t.reg .pred p;\n\tsetp.ne.u32 p, %4, 0;\n\t"
                 "tcgen05.mma.cta_group::1.kind::f16 [%0], [%1], %2, %3, {%5,%5,%5,%5}, p;\n\t}"
                 :: "r"(d), "r"(a), "l"(b), "r"(idesc), "r"(en), "r"(0u) : "memory");
}
#define STTM16U(ta, r) \
    asm volatile( \
        "tcgen05.st.sync.aligned.32x32b.x16.b32 [%0], " \
        "{%1, %2, %3, %4, %5, %6, %7, %8, " \
        " %9, %10, %11, %12, %13, %14, %15, %16};" \
        :: "r"(ta), \
           "r"((r)[0]),  "r"((r)[1]),  "r"((r)[2]),  "r"((r)[3]), \
           "r"((r)[4]),  "r"((r)[5]),  "r"((r)[6]),  "r"((r)[7]), \
           "r"((r)[8]),  "r"((r)[9]),  "r"((r)[10]), "r"((r)[11]), \
           "r"((r)[12]), "r"((r)[13]), "r"((r)[14]), "r"((r)[15]) \
        : "memory")
#define LDTM32(r, ta) \
    asm volatile( \
        "tcgen05.ld.sync.aligned.32x32b.x32.b32 " \
        "{%0, %1, %2, %3, %4, %5, %6, %7, " \
        " %8, %9, %10, %11, %12, %13, %14, %15, " \
        " %16, %17, %18, %19, %20, %21, %22, %23, " \
        " %24, %25, %26, %27, %28, %29, %30, %31}, [%32];" \
        : "=r"((r)[0]),  "=r"((r)[1]),  "=r"((r)[2]),  "=r"((r)[3]), \
          "=r"((r)[4]),  "=r"((r)[5]),  "=r"((r)[6]),  "=r"((r)[7]), \
          "=r"((r)[8]),  "=r"((r)[9]),  "=r"((r)[10]), "=r"((r)[11]), \
          "=r"((r)[12]), "=r"((r)[13]), "=r"((r)[14]), "=r"((r)[15]), \
          "=r"((r)[16]), "=r"((r)[17]), "=r"((r)[18]), "=r"((r)[19]), \
          "=r"((r)[20]), "=r"((r)[21]), "=r"((r)[22]), "=r"((r)[23]), \
          "=r"((r)[24]), "=r"((r)[25]), "=r"((r)[26]), "=r"((r)[27]), \
          "=r"((r)[28]), "=r"((r)[29]), "=r"((r)[30]), "=r"((r)[31]) \
        : "r"(ta))

__device__ __forceinline__ uint64_t mk_desc(uint32_t addr) {
    // SW128, version=1 (Blackwell), SBO=64, LBO=1
    return ((uint64_t)2 << 61) | ((uint64_t)1 << 46) | ((uint64_t)64 << 32) |
           ((uint64_t)1 << 16) | ((uint64_t)(addr >> 4) & 0x3FFF);
}
__device__ __forceinline__ uint32_t swoff(int r, int c16) {
    return (uint32_t)(((r >> 3) << 10) + ((r & 7) << 7) + (((c16 ^ (r & 7)) & 7) << 4));
}
// idesc bf16: c=F32(1), a=BF16(1), b=BF16(1), N=128, M=128
#define IDESC_BF ((1u << 4) | (1u << 7) | (1u << 10) | ((TN / 8) << 17) | ((TM / 16) << 24))
// TMEM: D cols 0..127; A stage st (st=0,1): 64 cols at 128+st*64
//   within stage: block b (b=0,1): hi 16 cols at b*32, lo 16 cols at b*32+16
#define TMEM_NCOLS 256
#define TM_D 0
#define TM_A(st) (128 + (st) * 64)
#endif  // USE_TC

// ==================== small kernels ====================
__global__ void k_anchors(const float* __restrict__ A, float* __restrict__ an_out,
                          int write_an) {
    int w = threadIdx.x >> 5, lane = threadIdx.x & 31;
    if (threadIdx.x < NEXP) g_cnt[threadIdx.x] = 0;
    float ss = 0.f;
    for (int d = lane; d < DIM; d += 32) { float v = A[w * DIM + d]; ss += v * v; }
    #pragma unroll
    for (int o = 16; o; o >>= 1) ss += __shfl_xor_sync(0xffffffffu, ss, o);
    float inv = 1.f / fmaxf(sqrtf(ss), EPSV);
    for (int d = lane; d < DIM; d += 32) {
        float v = A[w * DIM + d] * inv;
        g_anchors_n[w * DIM + d] = v;
        if (write_an) an_out[w * DIM + d] = v;
    }
}

__global__ void k_route(const float* __restrict__ x, float* __restrict__ out,
                        float* __restrict__ scores_out,
                        float* __restrict__ idx_out, int wflags) {
    {
        int t = blockIdx.x * blockDim.x + threadIdx.x;
        float4* o4 = (float4*)out;
        #pragma unroll
        for (int j = 0; j < 4; j++)
            o4[t * 4 + j] = make_float4(0.f, 0.f, 0.f, 0.f);
    }
    int wid = (blockIdx.x * blockDim.x + threadIdx.x) >> 5;
    int lane = threadIdx.x & 31;
    if (wid >= T_TOK) return;
    const float* xr = x + (size_t)wid * DIM;
    float xx = 0.f;
    float dt[NEXP];
    #pragma unroll
    for (int e = 0; e < NEXP; e++) dt[e] = 0.f;
    for (int d = lane; d < DIM; d += 32) {
        float xv = xr[d];
        xx += xv * xv;
        #pragma unroll
        for (int e = 0; e < NEXP; e++) dt[e] += xv * g_anchors_n[e * DIM + d];
    }
    #pragma unroll
    for (int o = 16; o; o >>= 1) {
        xx += __shfl_xor_sync(0xffffffffu, xx, o);
        #pragma unroll
        for (int e = 0; e < NEXP; e++) dt[e] += __shfl_xor_sync(0xffffffffu, dt[e], o);
    }
    if (lane == 0) {
        float inv = 1.f / fmaxf(sqrtf(xx), EPSV);
        float s[NEXP];
        #pragma unroll
        for (int e = 0; e < NEXP; e++) s[e] = dt[e] * inv;
        int i1 = 0; float v1 = s[0];
        #pragma unroll
        for (int e = 1; e < NEXP; e++) if (s[e] > v1) { v1 = s[e]; i1 = e; }
        int i2 = -1; float v2 = -1e30f;
        #pragma unroll
        for (int e = 0; e < NEXP; e++) if (e != i1 && s[e] > v2) { v2 = s[e]; i2 = e; }
        float e2 = expf(v2 - v1);
        float denom = 1.f / (1.f + e2);
        float g1 = denom, g2 = e2 * denom;
        int s1 = atomicAdd(&g_cnt[i1], 1);
        g_tok[i1][s1] = wid; g_gate[i1][s1] = g1;
        int s2 = atomicAdd(&g_cnt[i2], 1);
        g_tok[i2][s2] = wid; g_gate[i2][s2] = g2;
        if (wflags & 1) {
            #pragma unroll
            for (int e = 0; e < NEXP; e++) scores_out[wid * NEXP + e] = s[e];
        }
        if (wflags & 2) {
            idx_out[wid * 2 + 0] = (float)i1;
            idx_out[wid * 2 + 1] = (float)i2;
        }
    }
}

// ==================== GEMM1: H = gelu(Xg @ W1[e] + b1[e]) ====================
__global__ __launch_bounds__(256, 2)
void k_gemm1(const float* __restrict__ x, const float* __restrict__ W1,
             const float* __restrict__ b1) {
    const int e = blockIdx.z;
    const int count = g_cnt[e];
    const int m0 = blockIdx.y * TM;
    if (m0 >= count) return;
    const int n0 = blockIdx.x * TN;
    const int tid = threadIdx.x;
    const int wid = tid >> 5, lane = tid & 31;
    extern __shared__ char dynraw[];
    __shared__ int toks[TM];
    __shared__ int s_base;
    if (tid < TM) toks[tid] = g_tok[e][min(m0 + tid, count - 1)];
    if (tid == 0) {
        int b = 0;
        for (int i = 0; i < e; i++) b += g_cnt[i];
        s_base = b;
    }

#if USE_TC
    __shared__ __align__(8) unsigned long long s_mbar[2];
    __shared__ uint32_t s_tmem;
    const uint32_t sm = (sm2u32(dynraw) + 1023u) & ~1023u;
    if (tid == 0) { mbar_init(sm2u32(&s_mbar[0]), 1); mbar_init(sm2u32(&s_mbar[1]), 1); }
    if (wid == 0) {
        asm volatile("tcgen05.alloc.cta_group::1.sync.aligned.shared::cta.b32 [%0], %1;"
                     :: "r"(sm2u32(&s_tmem)), "r"((uint32_t)TMEM_NCOLS) : "memory");
        asm volatile("tcgen05.relinquish_alloc_permit.cta_group::1.sync.aligned;");
    }
    __syncthreads();
    const uint32_t tmem = s_tmem;
    const int base = s_base;
    const uint32_t mb0 = sm2u32(&s_mbar[0]);
    const float* Wbase = W1 + (size_t)e * DIM * FDIM + n0;

    const int NC = DIM / KC;   // 8
    for (int c = 0; c < NC; c++) {
        const int st = c & 1;
        const uint32_t mb = mb0 + st * 8;
        if (c >= 2) {
            mbar_wait(mb, ((c >> 1) - 1) & 1);
            asm volatile("tcgen05.fence::after_thread_sync;" ::: "memory");
        }
        const uint32_t B0 = sm + st * SMEM_STAGE;
        const int k0 = c * KC;
        if (tid < 128) {
            // A producer: row = tid, 64 k-values -> bf16 hi/lo -> TMEM
            const float* xr = x + (size_t)toks[tid] * DIM + k0;
            const uint32_t woff = ((uint32_t)(tid >> 5)) << 21;
            #pragma unroll
            for (int b = 0; b < 2; b++) {
                uint32_t hi[16], lo[16];
                #pragma unroll
                for (int q = 0; q < 8; q++) {
                    float4 v = *(const float4*)(xr + b * 32 + q * 4);
                    split2_bf16(v.x, v.y, hi[2 * q + 0], lo[2 * q + 0]);
                    split2_bf16(v.z, v.w, hi[2 * q + 1], lo[2 * q + 1]);
                }
                STTM16U(tmem + TM_A(st) + b * 32 + woff, hi);
                STTM16U(tmem + TM_A(st) + b * 32 + 16 + woff, lo);
            }
            asm volatile("tcgen05.wait::st.sync.aligned;" ::: "memory");
            asm volatile("tcgen05.fence::before_thread_sync;" ::: "memory");
        } else {
            // B producer: n = tid-128, 64 k-values -> bf16 hi/lo -> SMEM SW128
            const int n = tid - 128;
            const float* wp = Wbase + (size_t)k0 * FDIM + n;
            #pragma unroll
            for (int b = 0; b < 2; b++) {
                uint32_t hi[16], lo[16];
                #pragma unroll
                for (int i = 0; i < 16; i++) {
                    float v0 = wp[(size_t)(b * 32 + 2 * i + 0) * FDIM];
                    float v1 = wp[(size_t)(b * 32 + 2 * i + 1) * FDIM];
                    split2_bf16(v0, v1, hi[i], lo[i]);
                }
                const uint32_t Bblk = B0 + b * 16384;
                #pragma unroll
                for (int j = 0; j < 4; j++) {
                    sts128u(Bblk + swoff(n, j), hi + 4 * j);
                    sts128u(Bblk + swoff(n, 4 + j), lo + 4 * j);
                }
            }
            asm volatile("fence.proxy.async.shared::cta;" ::: "memory");
        }
        __syncthreads();
        if (wid == 0 && elect1()) {
            asm volatile("tcgen05.fence::after_thread_sync;" ::: "memory");
            #pragma unroll
            for (int b = 0; b < 2; b++) {
                uint64_t d = mk_desc(B0 + b * 16384);
                const uint32_t ah = tmem + TM_A(st) + b * 32, al = ah + 16;
                #pragma unroll
                for (int s = 0; s < 2; s++) {
                    mma_f16_ts(tmem + TM_D, ah + s * 8, d + s * 2, IDESC_BF,
                               (c | b | s) ? 1u : 0u);
                    mma_f16_ts(tmem + TM_D, ah + s * 8, d + 4 + s * 2, IDESC_BF, 1u);
                    mma_f16_ts(tmem + TM_D, al + s * 8, d + s * 2, IDESC_BF, 1u);
                }
            }
            tc_commit(mb);
        }
    }
    mbar_wait(mb0 + ((NC - 1) & 1) * 8, ((NC - 1) >> 1) & 1);
    asm volatile("tcgen05.fence::after_thread_sync;" ::: "memory");

    const int sp = wid & 3, half = wid >> 2;
    const int mi = m0 + sp * 32 + lane;
    const bool valid = mi < count;
    float* Hrow = g_H + (size_t)(base + (valid ? mi : 0)) * FDIM + n0;
    const float* bp = b1 + (size_t)e * FDIM + n0;
    #pragma unroll
    for (int cb = 0; cb < 2; cb++) {
        const uint32_t c0 = half * 64 + cb * 32;
        uint32_t rg[32];
        LDTM32(rg, tmem + TM_D + c0);
        asm volatile("tcgen05.wait::ld.sync.aligned;" ::: "memory");
        if (valid) {
            #pragma unroll
            for (int i = 0; i < 32; i += 4) {
                float4 o;
                o.x = gelu_f(__uint_as_float(rg[i + 0]) + bp[c0 + i + 0]);
                o.y = gelu_f(__uint_as_float(rg[i + 1]) + bp[c0 + i + 1]);
                o.z = gelu_f(__uint_as_float(rg[i + 2]) + bp[c0 + i + 2]);
                o.w = gelu_f(__uint_as_float(rg[i + 3]) + bp[c0 + i + 3]);
                *(float4*)(Hrow + c0 + i) = o;
            }
        }
    }
    asm volatile("tcgen05.fence::before_thread_sync;" ::: "memory");
    __syncthreads();
    if (tid == 0) { mbar_inval(mb0); mbar_inval(mb0 + 8); }
    if (wid == 0) {
        asm volatile("tcgen05.dealloc.cta_group::1.sync.aligned.b32 %0, %1;"
                     :: "r"(tmem), "r"((uint32_t)TMEM_NCOLS));
    }
#else
    // ---------- FFMA f32x2 fallback ----------
    float* As = (float*)dynraw;
    float* Bs = As + 16 * 132;
    __syncthreads();
    const int base = s_base;
    const int tx = tid & 15, ty = tid >> 4;
    unsigned long long acc[8][4];
    #pragma unroll
    for (int i = 0; i < 8; i++)
        #pragma unroll
        for (int j = 0; j < 4; j++) acc[i][j] = 0ull;
    const float* Wb = W1 + (size_t)e * DIM * FDIM + n0;
    for (int k0 = 0; k0 < DIM; k0 += 16) {
        #pragma unroll
        for (int j = 0; j < 2; j++) {
            int q = tid + j * 256;
            int m = q >> 2, kq = q & 3;
            float4 v = *(const float4*)(x + (size_t)toks[m] * DIM + k0 + kq * 4);
            As[(kq * 4 + 0) * 132 + m] = v.x; As[(kq * 4 + 1) * 132 + m] = v.y;
            As[(kq * 4 + 2) * 132 + m] = v.z; As[(kq * 4 + 3) * 132 + m] = v.w;
        }
        #pragma unroll
        for (int j = 0; j < 2; j++) {
            int q = tid + j * 256;
            int kk = q >> 5, nq = q & 31;
            float4 v = *(const float4*)(Wb + (size_t)(k0 + kk) * FDIM + nq * 4);
            *(float4*)&Bs[kk * 132 + nq * 4] = v;
        }
        __syncthreads();
        #pragma unroll
        for (int k = 0; k < 16; k++) {
            float4 a0 = *(float4*)&As[k * 132 + ty * 4];
            float4 a1 = *(float4*)&As[k * 132 + 64 + ty * 4];
            float4 b0 = *(float4*)&Bs[k * 132 + tx * 4];
            float4 b1r = *(float4*)&Bs[k * 132 + 64 + tx * 4];
            unsigned long long bb[4];
            bb[0] = ((const unsigned long long*)&b0)[0];
            bb[1] = ((const unsigned long long*)&b0)[1];
            bb[2] = ((const unsigned long long*)&b1r)[0];
            bb[3] = ((const unsigned long long*)&b1r)[1];
            float av[8] = {a0.x, a0.y, a0.z, a0.w, a1.x, a1.y, a1.z, a1.w};
            #pragma unroll
            for (int i = 0; i < 8; i++) {
                unsigned long long aa = pack2(av[i]);
                #pragma unroll
                for (int jj = 0; jj < 4; jj++) acc[i][jj] = fma2(aa, bb[jj], acc[i][jj]);
            }
        }
        __syncthreads();
    }
    #pragma unroll
    for (int i = 0; i < 8; i++) {
        int mloc = (i < 4) ? (ty * 4 + i) : (64 + ty * 4 + (i - 4));
        int mi = m0 + mloc;
        if (mi >= count) continue;
        float* Hrow = g_H + (size_t)(base + mi) * FDIM + n0;
        #pragma unroll
        for (int jj = 0; jj < 4; jj++) {
            int nloc = (jj < 2) ? (tx * 4 + jj * 2) : (64 + tx * 4 + (jj - 2) * 2);
            float2 v = *(float2*)&acc[i][jj];
            float h0 = gelu_f(v.x + b1[e * FDIM + n0 + nloc]);
            float h1 = gelu_f(v.y + b1[e * FDIM + n0 + nloc + 1]);
            *(float2*)(Hrow + nloc) = make_float2(h0, h1);
        }
    }
#endif
}

// ==================== GEMM2: out += gate * (H @ W2[e] + b2[e]) ====================
__global__ __launch_bounds__(256, 2)
void k_gemm2(const float* __restrict__ W2, const float* __restrict__ b2,
             float* __restrict__ out) {
    const int e = blockIdx.z;
    const int count = g_cnt[e];
    const int m0 = blockIdx.y * TM;
    if (m0 >= count) return;
    const int n0 = blockIdx.x * TN;
    const int tid = threadIdx.x;
    const int wid = tid >> 5, lane = tid & 31;
    extern __shared__ char dynraw[];
    __shared__ int   toks[TM];
    __shared__ float gts[TM];
    __shared__ int s_base;
    if (tid < TM) {
        int mi = min(m0 + tid, count - 1);
        toks[tid] = g_tok[e][mi];
        gts[tid]  = g_gate[e][mi];
    }
    if (tid == 0) {
        int b = 0;
        for (int i = 0; i < e; i++) b += g_cnt[i];
        s_base = b;
    }

#if USE_TC
    __shared__ __align__(8) unsigned long long s_mbar[2];
    __shared__ uint32_t s_tmem;
    const uint32_t sm = (sm2u32(dynraw) + 1023u) & ~1023u;
    if (tid == 0) { mbar_init(sm2u32(&s_mbar[0]), 1); mbar_init(sm2u32(&s_mbar[1]), 1); }
    if (wid == 0) {
        asm volatile("tcgen05.alloc.cta_group::1.sync.aligned.shared::cta.b32 [%0], %1;"
                     :: "r"(sm2u32(&s_tmem)), "r"((uint32_t)TMEM_NCOLS) : "memory");
        asm volatile("tcgen05.relinquish_alloc_permit.cta_group::1.sync.aligned;");
    }
    __syncthreads();
    const uint32_t tmem = s_tmem;
    const int base = s_base;
    const uint32_t mb0 = sm2u32(&s_mbar[0]);
    const float* Wbase = W2 + (size_t)e * FDIM * DIM + n0;

    const int NC = FDIM / KC;   // 32
    for (int c = 0; c < NC; c++) {
        const int st = c & 1;
        const uint32_t mb = mb0 + st * 8;
        if (c >= 2) {
            mbar_wait(mb, ((c >> 1) - 1) & 1);
            asm volatile("tcgen05.fence::after_thread_sync;" ::: "memory");
        }
        const uint32_t B0 = sm + st * SMEM_STAGE;
        const int k0 = c * KC;
        if (tid < 128) {
            const int rowg = base + min(m0 + tid, count - 1);
            const float* hr = g_H + (size_t)rowg * FDIM + k0;
            const uint32_t woff = ((uint32_t)(tid >> 5)) << 21;
            #pragma unroll
            for (int b = 0; b < 2; b++) {
                uint32_t hi[16], lo[16];
                #pragma unroll
                for (int q = 0; q < 8; q++) {
                    float4 v = *(const float4*)(hr + b * 32 + q * 4);
                    split2_bf16(v.x, v.y, hi[2 * q + 0], lo[2 * q + 0]);
                    split2_bf16(v.z, v.w, hi[2 * q + 1], lo[2 * q + 1]);
                }
                STTM16U(tmem + TM_A(st) + b * 32 + woff, hi);
                STTM16U(tmem + TM_A(st) + b * 32 + 16 + woff, lo);
            }
            asm volatile("tcgen05.wait::st.sync.aligned;" ::: "memory");
            asm volatile("tcgen05.fence::before_thread_sync;" ::: "memory");
        } else {
            const int n = tid - 128;
            const float* wp = Wbase + (size_t)k0 * DIM + n;
            #pragma unroll
            for (int b = 0; b < 2; b++) {
                uint32_t hi[16], lo[16];
                #pragma unroll
                for (int i = 0; i < 16; i++) {
                    float v0 = wp[(size_t)(b * 32 + 2 * i + 0) * DIM];
                    float v1 = wp[(size_t)(b * 32 + 2 * i + 1) * DIM];
                    split2_bf16(v0, v1, hi[i], lo[i]);
                }
                const uint32_t Bblk = B0 + b * 16384;
                #pragma unroll
                for (int j = 0; j < 4; j++) {
                    sts128u(Bblk + swoff(n, j), hi + 4 * j);
                    sts128u(Bblk + swoff(n, 4 + j), lo + 4 * j);
                }
            }
            asm volatile("fence.proxy.async.shared::cta;" ::: "memory");
        }
        __syncthreads();
        if (wid == 0 && elect1()) {
            asm volatile("tcgen05.fence::after_thread_sync;" ::: "memory");
            #pragma unroll
            for (int b = 0; b < 2; b++) {
                uint64_t d = mk_desc(B0 + b * 16384);
                const uint32_t ah = tmem + TM_A(st) + b * 32, al = ah + 16;
                #pragma unroll
                for (int s = 0; s < 2; s++) {
                    mma_f16_ts(tmem + TM_D, ah + s * 8, d + s * 2, IDESC_BF,
                               (c | b | s) ? 1u : 0u);
                    mma_f16_ts(tmem + TM_D, ah + s * 8, d + 4 + s * 2, IDESC_BF, 1u);
                    mma_f16_ts(tmem + TM_D, al + s * 8, d + s * 2, IDESC_BF, 1u);
                }
            }
            tc_commit(mb);
        }
    }
    mbar_wait(mb0 + ((NC - 1) & 1) * 8, ((NC - 1) >> 1) & 1);
    asm volatile("tcgen05.fence::after_thread_sync;" ::: "memory");

    const int sp = wid & 3, half = wid >> 2;
    const int ml = sp * 32 + lane;
    const int mi = m0 + ml;
    const bool valid = mi < count;
    const int tok = toks[ml];
    const float gate = gts[ml];
    float* orow = out + (size_t)tok * DIM + n0;
    const float* bp = b2 + (size_t)e * DIM + n0;
    #pragma unroll
    for (int cb = 0; cb < 2; cb++) {
        const uint32_t c0 = half * 64 + cb * 32;
        uint32_t rg[32];
        LDTM32(rg, tmem + TM_D + c0);
        asm volatile("tcgen05.wait::ld.sync.aligned;" ::: "memory");
        if (valid) {
            #pragma unroll
            for (int i = 0; i < 32; i++) {
                float y = __uint_as_float(rg[i]) + bp[c0 + i];
                atomicAdd(orow + c0 + i, gate * y);
            }
        }
    }
    asm volatile("tcgen05.fence::before_thread_sync;" ::: "memory");
    __syncthreads();
    if (tid == 0) { mbar_inval(mb0); mbar_inval(mb0 + 8); }
    if (wid == 0) {
        asm volatile("tcgen05.dealloc.cta_group::1.sync.aligned.b32 %0, %1;"
                     :: "r"(tmem), "r"((uint32_t)TMEM_NCOLS));
    }
#else
    // ---------- FFMA f32x2 fallback ----------
    float* As = (float*)dynraw;
    float* Bs = As + 16 * 132;
    __syncthreads();
    const int base = s_base;
    const int tx = tid & 15, ty = tid >> 4;
    unsigned long long acc[8][4];
    #pragma unroll
    for (int i = 0; i < 8; i++)
        #pragma unroll
        for (int j = 0; j < 4; j++) acc[i][j] = 0ull;
    const float* Wb = W2 + (size_t)e * FDIM * DIM + n0;
    for (int k0 = 0; k0 < FDIM; k0 += 16) {
        #pragma unroll
        for (int j = 0; j < 2; j++) {
            int q = tid + j * 256;
            int m = q >> 2, kq = q & 3;
            int rowg = base + min(m0 + m, count - 1);
            float4 v = *(const float4*)(g_H + (size_t)rowg * FDIM + k0 + kq * 4);
            As[(kq * 4 + 0) * 132 + m] = v.x; As[(kq * 4 + 1) * 132 + m] = v.y;
            As[(kq * 4 + 2) * 132 + m] = v.z; As[(kq * 4 + 3) * 132 + m] = v.w;
        }
        #pragma unroll
        for (int j = 0; j < 2; j++) {
            int q = tid + j * 256;
            int kk = q >> 5, nq = q & 31;
            float4 v = *(const float4*)(Wb + (size_t)(k0 + kk) * DIM + nq * 4);
            *(float4*)&Bs[kk * 132 + nq * 4] = v;
        }
        __syncthreads();
        #pragma unroll
        for (int k = 0; k < 16; k++) {
            float4 a0 = *(float4*)&As[k * 132 + ty * 4];
            float4 a1 = *(float4*)&As[k * 132 + 64 + ty * 4];
            float4 b0 = *(float4*)&Bs[k * 132 + tx * 4];
            float4 b1r = *(float4*)&Bs[k * 132 + 64 + tx * 4];
            unsigned long long bb[4];
            bb[0] = ((const unsigned long long*)&b0)[0];
            bb[1] = ((const unsigned long long*)&b0)[1];
            bb[2] = ((const unsigned long long*)&b1r)[0];
            bb[3] = ((const unsigned long long*)&b1r)[1];
            float av[8] = {a0.x, a0.y, a0.z, a0.w, a1.x, a1.y, a1.z, a1.w};
            #pragma unroll
            for (int i = 0; i < 8; i++) {
                unsigned long long aa = pack2(av[i]);
                #pragma unroll
                for (int jj = 0; jj < 4; jj++) acc[i][jj] = fma2(aa, bb[jj], acc[i][jj]);
            }
        }
        __syncthreads();
    }
    #pragma unroll
    for (int i = 0; i < 8; i++) {
        int mloc = (i < 4) ? (ty * 4 + i) : (64 + ty * 4 + (i - 4));
        int mi = m0 + mloc;
        if (mi >= count) continue;
        int tok = toks[mloc];
        float g = gts[mloc];
        float* orow = out + (size_t)tok * DIM + n0;
        #pragma unroll
        for (int jj = 0; jj < 4; jj++) {
            int nloc = (jj < 2) ? (tx * 4 + jj * 2) : (64 + tx * 4 + (jj - 2) * 2);
            float2 v = *(float2*)&acc[i][jj];
            atomicAdd(orow + nloc,     g * (v.x + b2[e * DIM + n0 + nloc]));
            atomicAdd(orow + nloc + 1, g * (v.y + b2[e * DIM + n0 + nloc + 1]));
        }
    }
#endif
}

// ==================== launch ====================
extern "C" void kernel_launch(void* const* d_in, const int* in_sizes, int n_in,
                              void* d_out, int out_size) {
    const float* x       = (const float*)d_in[0];
    const float* anchors = (const float*)d_in[1];
    const float* W1      = (const float*)d_in[2];
    const float* b1      = (const float*)d_in[3];
    const float* W2      = (const float*)d_in[4];
    const float* b2      = (const float*)d_in[5];
    float* out = (float*)d_out;

    static int attr_done = 0;
    if (!attr_done) {
        cudaFuncSetAttribute(k_gemm1, cudaFuncAttributeMaxDynamicSharedMemorySize, SMEM_DYN);
        cudaFuncSetAttribute(k_gemm2, cudaFuncAttributeMaxDynamicSharedMemorySize, SMEM_DYN);
        attr_done = 1;
    }

    const int OUT_END = T_TOK * DIM;
    const int AN_END  = OUT_END + NEXP * DIM;
    const int SC_END  = AN_END + T_TOK * NEXP;
    const int IX_END  = SC_END + T_TOK * 2;
    int write_an = (out_size >= AN_END) ? 1 : 0;
    int wflags = ((out_size >= SC_END) ? 1 : 0) | ((out_size >= IX_END) ? 2 : 0);

    k_anchors<<<1, 256>>>(anchors, out + OUT_END, write_an);
    k_route<<<512, 256>>>(x, out, out + AN_END, out + SC_END, wflags);
    dim3 g1(FDIM / TN, T_TOK / TM, NEXP);
    k_gemm1<<<g1, 256, SMEM_DYN>>>(x, W1, b1);
    dim3 g2(DIM / TN, T_TOK / TM, NEXP);
    k_gemm2<<<g2, 256, SMEM_DYN>>>(W2, b2, out);
}

// round 6
// speedup vs baseline: 2.8778x; 1.0139x over previous
#include <cuda_runtime.h>
#include <cstdint>

#define T_TOK 4096
#define DIM   512
#define FDIM  2048
#define NEXP  8
#define EPSV  1e-8f

#define TM   128
#define TN   128
#define KC   32
#define NSTG 4

#if defined(__CUDA_ARCH__) && defined(__CUDA_ARCH_FEAT_SM103_ALL)
#define USE_TC 1
#else
#define USE_TC 0
#endif

#define SMEM_STAGE 16384            // hi block 8KB + lo block 8KB (128 rows x 64B, SW64)
#define SMEM_DYN   (NSTG * SMEM_STAGE + 1024)
#define NTHREADS   288

// -------- scratch (static device globals; no runtime alloc) --------
__device__ float g_anchors_n[NEXP * DIM];
__device__ int   g_cnt[NEXP];
__device__ int   g_tok[NEXP][T_TOK];
__device__ float g_gate[NEXP][T_TOK];
__device__ float g_H[(2 * T_TOK) * FDIM];   // 8192 x 2048 fp32

// ==================== helpers ====================
__device__ __forceinline__ float gelu_f(float h) {
    return 0.5f * h * (1.f + erff(h * 0.7071067811865476f));
}
__device__ __forceinline__ unsigned long long pack2(float a) {
    unsigned long long r;
    asm("mov.b64 %0, {%1, %1};" : "=l"(r) : "f"(a));
    return r;
}
__device__ __forceinline__ unsigned long long fma2(unsigned long long a,
                                                   unsigned long long b,
                                                   unsigned long long c) {
    unsigned long long d;
    asm("fma.rn.f32x2 %0, %1, %2, %3;" : "=l"(d) : "l"(a), "l"(b), "l"(c));
    return d;
}

#if USE_TC
__device__ __forceinline__ uint32_t sm2u32(const void* p) {
    uint32_t a;
    asm("{ .reg .u64 t; cvta.to.shared.u64 t, %1; cvt.u32.u64 %0, t; }" : "=r"(a) : "l"(p));
    return a;
}
__device__ __forceinline__ bool elect1() {
    uint32_t r;
    asm volatile("{ .reg .pred p; elect.sync _|p, 0xFFFFFFFF; selp.b32 %0, 1, 0, p; }" : "=r"(r));
    return r != 0;
}
__device__ __forceinline__ void split2_bf16(float v0, float v1, uint32_t& hw, uint32_t& lw) {
    asm("cvt.rn.satfinite.bf16x2.f32 %0, %1, %2;" : "=r"(hw) : "f"(v1), "f"(v0));
    float h0 = __uint_as_float(hw << 16);
    float h1 = __uint_as_float(hw & 0xffff0000u);
    asm("cvt.rn.satfinite.bf16x2.f32 %0, %1, %2;" : "=r"(lw) : "f"(v1 - h1), "f"(v0 - h0));
}
__device__ __forceinline__ void sts128u(uint32_t a, const uint32_t* w) {
    asm volatile("st.shared.v4.b32 [%0], {%1,%2,%3,%4};"
                 :: "r"(a), "r"(w[0]), "r"(w[1]), "r"(w[2]), "r"(w[3]) : "memory");
}
__device__ __forceinline__ void mbar_init(uint32_t a, uint32_t c) {
    asm volatile("mbarrier.init.shared.b64 [%0], %1;" :: "r"(a), "r"(c) : "memory");
}
__device__ __forceinline__ void mbar_inval(uint32_t a) {
    asm volatile("mbarrier.inval.shared.b64 [%0];" :: "r"(a) : "memory");
}
__device__ __forceinline__ void mbar_arrive(uint32_t a) {
    asm volatile("mbarrier.arrive.shared.b64 _, [%0];" :: "r"(a) : "memory");
}
__device__ __forceinline__ void mbar_wait(uint32_t a, uint32_t ph) {
    uint32_t done;
    asm volatile("{\n\t.reg .pred p;\n\t"
                 "mbarrier.try_wait.parity.acquire.cta.shared::cta.b64 p, [%1], %2;\n\t"
                 "selp.b32 %0, 1, 0, p;\n\t}"
                 : "=r"(done) : "r"(a), "r"(ph) : "memory");
    if (!done) {
        asm volatile("{\n\t.reg .pred P1;\n\t"
                     "LW%=:\n\t"
                     "mbarrier.try_wait.parity.acquire.cta.shared::cta.b64 P1, [%0], %1, 0x989680;\n\t"
                     "@P1 bra.uni LD%=;\n\t"
                     "bra.uni LW%=;\n\t"
                     "LD%=:\n\t}"
                     :: "r"(a), "r"(ph) : "memory");
    }
}
__device__ __forceinline__ void tc_commit(uint32_t mb) {
    asm volatile("tcgen05.commit.cta_group::1.mbarrier::arrive::one.shared::cluster.b64 [%0];"
                 :: "r"(mb) : "memory");
}
__device__ __forceinline__ void mma_f16_ts(uint32_t d, uint32_t a, uint64_t b,
                                           uint32_t idesc, uint32_t en) {
    asm volatile("{\n\t.reg .pred p;\n\tsetp.ne.u32 p, %4, 0;\n\t"
                 "tcgen05.mma.cta_group::1.kind::f16 [%0], [%1], %2, %3, {%5,%5,%5,%5}, p;\n\t}"
                 :: "r"(d), "r"(a), "l"(b), "r"(idesc), "r"(en), "r"(0u) : "memory");
}
#define STTM16U(ta, r) \
    asm volatile( \
        "tcgen05.st.sync.aligned.32x32b.x16.b32 [%0], " \
        "{%1, %2, %3, %4, %5, %6, %7, %8, " \
        " %9, %10, %11, %12, %13, %14, %15, %16};" \
        :: "r"(ta), \
           "r"((r)[0]),  "r"((r)[1]),  "r"((r)[2]),  "r"((r)[3]), \
           "r"((r)[4]),  "r"((r)[5]),  "r"((r)[6]),  "r"((r)[7]), \
           "r"((r)[8]),  "r"((r)[9]),  "r"((r)[10]), "r"((r)[11]), \
           "r"((r)[12]), "r"((r)[13]), "r"((r)[14]), "r"((r)[15]) \
        : "memory")
#define LDTM32(r, ta) \
    asm volatile( \
        "tcgen05.ld.sync.aligned.32x32b.x32.b32 " \
        "{%0, %1, %2, %3, %4, %5, %6, %7, " \
        " %8, %9, %10, %11, %12, %13, %14, %15, " \
        " %16, %17, %18, %19, %20, %21, %22, %23, " \
        " %24, %25, %26, %27, %28, %29, %30, %31}, [%32];" \
        : "=r"((r)[0]),  "=r"((r)[1]),  "=r"((r)[2]),  "=r"((r)[3]), \
          "=r"((r)[4]),  "=r"((r)[5]),  "=r"((r)[6]),  "=r"((r)[7]), \
          "=r"((r)[8]),  "=r"((r)[9]),  "=r"((r)[10]), "=r"((r)[11]), \
          "=r"((r)[12]), "=r"((r)[13]), "=r"((r)[14]), "=r"((r)[15]), \
          "=r"((r)[16]), "=r"((r)[17]), "=r"((r)[18]), "=r"((r)[19]), \
          "=r"((r)[20]), "=r"((r)[21]), "=r"((r)[22]), "=r"((r)[23]), \
          "=r"((r)[24]), "=r"((r)[25]), "=r"((r)[26]), "=r"((r)[27]), \
          "=r"((r)[28]), "=r"((r)[29]), "=r"((r)[30]), "=r"((r)[31]) \
        : "r"(ta))

// SW64 descriptor: layout=4, version=1, SBO=32 (512B per 8-row group), LBO=1
__device__ __forceinline__ uint64_t mk_desc64(uint32_t addr) {
    return ((uint64_t)4 << 61) | ((uint64_t)1 << 46) | ((uint64_t)32 << 32) |
           ((uint64_t)1 << 16) | ((uint64_t)(addr >> 4) & 0x3FFF);
}
// SW64 byte offset: block of 128 rows x 64B; row r, 16B-chunk c16 (0..3)
__device__ __forceinline__ uint32_t swoff64(int r, int c16) {
    return (uint32_t)(((r >> 3) << 9) + ((r & 7) << 6) + (((c16 ^ ((r >> 1) & 3)) & 3) << 4));
}
// idesc bf16: c=F32(1), a=BF16(1), b=BF16(1), N=128, M=128
#define IDESC_BF ((1u << 4) | (1u << 7) | (1u << 10) | ((TN / 8) << 17) | ((TM / 16) << 24))
// TMEM: D cols 0..127; A stage st: 32 cols at 128+st*32 (hi 16 | lo 16)
#define TMEM_NCOLS 256
#define TM_D 0
#define TM_A(st) (128 + (st) * 32)
#endif  // USE_TC

// ==================== small kernels ====================
__global__ void k_anchors(const float* __restrict__ A, float* __restrict__ an_out,
                          int write_an) {
    int w = threadIdx.x >> 5, lane = threadIdx.x & 31;
    if (threadIdx.x < NEXP) g_cnt[threadIdx.x] = 0;
    float ss = 0.f;
    for (int d = lane; d < DIM; d += 32) { float v = A[w * DIM + d]; ss += v * v; }
    #pragma unroll
    for (int o = 16; o; o >>= 1) ss += __shfl_xor_sync(0xffffffffu, ss, o);
    float inv = 1.f / fmaxf(sqrtf(ss), EPSV);
    for (int d = lane; d < DIM; d += 32) {
        float v = A[w * DIM + d] * inv;
        g_anchors_n[w * DIM + d] = v;
        if (write_an) an_out[w * DIM + d] = v;
    }
}

__global__ void k_route(const float* __restrict__ x, float* __restrict__ out,
                        float* __restrict__ scores_out,
                        float* __restrict__ idx_out, int wflags) {
    {
        int t = blockIdx.x * blockDim.x + threadIdx.x;
        float4* o4 = (float4*)out;
        #pragma unroll
        for (int j = 0; j < 4; j++)
            o4[t * 4 + j] = make_float4(0.f, 0.f, 0.f, 0.f);
    }
    int wid = (blockIdx.x * blockDim.x + threadIdx.x) >> 5;
    int lane = threadIdx.x & 31;
    if (wid >= T_TOK) return;
    const float* xr = x + (size_t)wid * DIM;
    float xx = 0.f;
    float dt[NEXP];
    #pragma unroll
    for (int e = 0; e < NEXP; e++) dt[e] = 0.f;
    for (int d = lane; d < DIM; d += 32) {
        float xv = xr[d];
        xx += xv * xv;
        #pragma unroll
        for (int e = 0; e < NEXP; e++) dt[e] += xv * g_anchors_n[e * DIM + d];
    }
    #pragma unroll
    for (int o = 16; o; o >>= 1) {
        xx += __shfl_xor_sync(0xffffffffu, xx, o);
        #pragma unroll
        for (int e = 0; e < NEXP; e++) dt[e] += __shfl_xor_sync(0xffffffffu, dt[e], o);
    }
    if (lane == 0) {
        float inv = 1.f / fmaxf(sqrtf(xx), EPSV);
        float s[NEXP];
        #pragma unroll
        for (int e = 0; e < NEXP; e++) s[e] = dt[e] * inv;
        int i1 = 0; float v1 = s[0];
        #pragma unroll
        for (int e = 1; e < NEXP; e++) if (s[e] > v1) { v1 = s[e]; i1 = e; }
        int i2 = -1; float v2 = -1e30f;
        #pragma unroll
        for (int e = 0; e < NEXP; e++) if (e != i1 && s[e] > v2) { v2 = s[e]; i2 = e; }
        float e2 = expf(v2 - v1);
        float denom = 1.f / (1.f + e2);
        float g1 = denom, g2 = e2 * denom;
        int s1 = atomicAdd(&g_cnt[i1], 1);
        g_tok[i1][s1] = wid; g_gate[i1][s1] = g1;
        int s2 = atomicAdd(&g_cnt[i2], 1);
        g_tok[i2][s2] = wid; g_gate[i2][s2] = g2;
        if (wflags & 1) {
            #pragma unroll
            for (int e = 0; e < NEXP; e++) scores_out[wid * NEXP + e] = s[e];
        }
        if (wflags & 2) {
            idx_out[wid * 2 + 0] = (float)i1;
            idx_out[wid * 2 + 1] = (float)i2;
        }
    }
}

#if USE_TC
// ========== shared warp-specialized GEMM mainloop (device inline) ==========
// Computes D(tmem cols 0..127) = A(128 rows) x B(128 cols)^T over K=NC*KC,
// A rows loaded from arow[r] + k, B cols from wcol + n with leading dim wld.
__device__ __forceinline__ void gemm_mainloop(
    const float* __restrict__* arows,          // per-row base pointers (smem array)
    const float* __restrict__ wcol, int wld,
    int NC, uint32_t sm, uint32_t tmem,
    uint32_t mb_done, uint32_t mb_fa, uint32_t mb_fb)
{
    const int tid = threadIdx.x;
    const int wid = tid >> 5;
    if (wid < 4) {
        // ---- A producer: row = tid (0..127) ----
        const uint32_t woff = ((uint32_t)wid) << 21;
        for (int c = 0; c < NC; c++) {
            const int st = c & (NSTG - 1);
            if (c >= NSTG) {
                mbar_wait(mb_done + st * 8, ((c >> 2) + 1) & 1);
                asm volatile("tcgen05.fence::after_thread_sync;" ::: "memory");
            }
            const float* xr = arows[tid] + c * KC;
            uint32_t hi[8], lo[8];
            #pragma unroll
            for (int q = 0; q < 8; q++) {
                float4 v = *(const float4*)(xr + q * 4);
                uint32_t h0, l0, h1, l1;
                split2_bf16(v.x, v.y, h0, l0);
                split2_bf16(v.z, v.w, h1, l1);
                hi[q] = h0; lo[q] = l0;
                // stash second pair interleaved: store as [2q],[2q+1] pattern below
                hi[q] = h0; lo[q] = l0;
                // second words handled in arrays below
                ((uint32_t*)hi)[q] = h0; ((uint32_t*)lo)[q] = l0;
                (void)h1; (void)l1;
                // we need 16 words; expand arrays:
            }
            // redo cleanly with 16-word arrays
            uint32_t hw[16], lw[16];
            #pragma unroll
            for (int q = 0; q < 8; q++) {
                float4 v = *(const float4*)(xr + q * 4);
                split2_bf16(v.x, v.y, hw[2 * q + 0], lw[2 * q + 0]);
                split2_bf16(v.z, v.w, hw[2 * q + 1], lw[2 * q + 1]);
            }
            STTM16U(tmem + TM_A(st) + woff, hw);
            STTM16U(tmem + TM_A(st) + 16 + woff, lw);
            asm volatile("tcgen05.wait::st.sync.aligned;" ::: "memory");
            asm volatile("tcgen05.fence::before_thread_sync;" ::: "memory");
            mbar_arrive(mb_fa + st * 8);
        }
    } else if (wid < 8) {
        // ---- B producer: n = tid - 128 (0..127) ----
        const int n = tid - 128;
        for (int c = 0; c < NC; c++) {
            const int st = c & (NSTG - 1);
            if (c >= NSTG) mbar_wait(mb_done + st * 8, ((c >> 2) + 1) & 1);
            const float* wp = wcol + (size_t)(c * KC) * wld + n;
            float v[KC];
            #pragma unroll
            for (int k = 0; k < KC; k++) v[k] = wp[(size_t)k * wld];
            uint32_t hw[16], lw[16];
            #pragma unroll
            for (int k = 0; k < 16; k++)
                split2_bf16(v[2 * k], v[2 * k + 1], hw[k], lw[k]);
            const uint32_t Bhi = sm + st * SMEM_STAGE;
            const uint32_t Blo = Bhi + 8192;
            #pragma unroll
            for (int j = 0; j < 4; j++) {
                sts128u(Bhi + swoff64(n, j), hw + 4 * j);
                sts128u(Blo + swoff64(n, j), lw + 4 * j);
            }
            asm volatile("fence.proxy.async.shared::cta;" ::: "memory");
            mbar_arrive(mb_fb + st * 8);
        }
    } else {
        // ---- MMA issuer: warp 8, single elected thread ----
        if (elect1()) {
            for (int c = 0; c < NC; c++) {
                const int st = c & (NSTG - 1);
                const uint32_t ph = (c >> 2) & 1;
                mbar_wait(mb_fa + st * 8, ph);
                mbar_wait(mb_fb + st * 8, ph);
                asm volatile("tcgen05.fence::after_thread_sync;" ::: "memory");
                const uint32_t Bhi = sm + st * SMEM_STAGE;
                uint64_t dh = mk_desc64(Bhi), dl = mk_desc64(Bhi + 8192);
                const uint32_t ah = tmem + TM_A(st), al = ah + 16;
                #pragma unroll
                for (int s2 = 0; s2 < 2; s2++) {
                    mma_f16_ts(tmem + TM_D, ah + s2 * 8, dh + s2 * 2, IDESC_BF,
                               (c | s2) ? 1u : 0u);
                    mma_f16_ts(tmem + TM_D, ah + s2 * 8, dl + s2 * 2, IDESC_BF, 1u);
                    mma_f16_ts(tmem + TM_D, al + s2 * 8, dh + s2 * 2, IDESC_BF, 1u);
                }
                tc_commit(mb_done + st * 8);
            }
        }
    }
}
#endif  // USE_TC

// ==================== GEMM1: H = gelu(Xg @ W1[e] + b1[e]) ====================
__global__ __launch_bounds__(NTHREADS, 2)
void k_gemm1(const float* __restrict__ x, const float* __restrict__ W1,
             const float* __restrict__ b1) {
    const int e = blockIdx.z;
    const int count = g_cnt[e];
    const int m0 = blockIdx.y * TM;
    if (m0 >= count) return;
    const int n0 = blockIdx.x * TN;
    const int tid = threadIdx.x;
    const int wid = tid >> 5, lane = tid & 31;
    extern __shared__ char dynraw[];
    __shared__ int toks[TM];
    __shared__ int s_base;
    if (tid < TM) toks[tid] = g_tok[e][min(m0 + tid, count - 1)];
    if (tid == 0) {
        int b = 0;
        for (int i = 0; i < e; i++) b += g_cnt[i];
        s_base = b;
    }

#if USE_TC
    __shared__ __align__(8) unsigned long long s_bar[3 * NSTG];
    __shared__ uint32_t s_tmem;
    __shared__ const float* s_arows[TM];
    const uint32_t sm = (sm2u32(dynraw) + 1023u) & ~1023u;
    if (tid == 0) {
        for (int s = 0; s < NSTG; s++) {
            mbar_init(sm2u32(&s_bar[s]), 1);                 // done
            mbar_init(sm2u32(&s_bar[NSTG + s]), 128);        // fullA
            mbar_init(sm2u32(&s_bar[2 * NSTG + s]), 128);    // fullB
        }
    }
    if (tid < TM) s_arows[tid] = x + (size_t)toks[tid] * DIM;
    if (wid == 0) {
        asm volatile("tcgen05.alloc.cta_group::1.sync.aligned.shared::cta.b32 [%0], %1;"
                     :: "r"(sm2u32(&s_tmem)), "r"((uint32_t)TMEM_NCOLS) : "memory");
        asm volatile("tcgen05.relinquish_alloc_permit.cta_group::1.sync.aligned;");
    }
    __syncthreads();
    const uint32_t tmem = s_tmem;
    const int base = s_base;
    const uint32_t mb_done = sm2u32(&s_bar[0]);
    const uint32_t mb_fa   = sm2u32(&s_bar[NSTG]);
    const uint32_t mb_fb   = sm2u32(&s_bar[2 * NSTG]);

    const int NC = DIM / KC;   // 16
    gemm_mainloop(s_arows, W1 + (size_t)e * DIM * FDIM + n0, FDIM,
                  NC, sm, tmem, mb_done, mb_fa, mb_fb);
    __syncthreads();
    mbar_wait(mb_done + ((NC - 1) & (NSTG - 1)) * 8, ((NC - 1) >> 2) & 1);
    asm volatile("tcgen05.fence::after_thread_sync;" ::: "memory");

    if (wid < 8) {
        const int sp = wid & 3, half = wid >> 2;
        const int mi = m0 + sp * 32 + lane;
        const bool valid = mi < count;
        float* Hrow = g_H + (size_t)(base + (valid ? mi : 0)) * FDIM + n0;
        const float* bp = b1 + (size_t)e * FDIM + n0;
        #pragma unroll
        for (int cb = 0; cb < 2; cb++) {
            const uint32_t c0 = half * 64 + cb * 32;
            uint32_t rg[32];
            LDTM32(rg, tmem + TM_D + c0);
            asm volatile("tcgen05.wait::ld.sync.aligned;" ::: "memory");
            if (valid) {
                #pragma unroll
                for (int i = 0; i < 32; i += 4) {
                    float4 o;
                    o.x = gelu_f(__uint_as_float(rg[i + 0]) + bp[c0 + i + 0]);
                    o.y = gelu_f(__uint_as_float(rg[i + 1]) + bp[c0 + i + 1]);
                    o.z = gelu_f(__uint_as_float(rg[i + 2]) + bp[c0 + i + 2]);
                    o.w = gelu_f(__uint_as_float(rg[i + 3]) + bp[c0 + i + 3]);
                    *(float4*)(Hrow + c0 + i) = o;
                }
            }
        }
        asm volatile("tcgen05.fence::before_thread_sync;" ::: "memory");
    }
    __syncthreads();
    if (tid == 0)
        for (int s = 0; s < 3 * NSTG; s++) mbar_inval(sm2u32(&s_bar[s]));
    if (wid == 0) {
        asm volatile("tcgen05.dealloc.cta_group::1.sync.aligned.b32 %0, %1;"
                     :: "r"(tmem), "r"((uint32_t)TMEM_NCOLS));
    }
#else
    // ---------- FFMA f32x2 fallback (tid<256 active) ----------
    float* As = (float*)dynraw;
    float* Bs = As + 16 * 132;
    __syncthreads();
    const int base = s_base;
    const int tx = tid & 15, ty = tid >> 4;
    unsigned long long acc[8][4];
    #pragma unroll
    for (int i = 0; i < 8; i++)
        #pragma unroll
        for (int j = 0; j < 4; j++) acc[i][j] = 0ull;
    const float* Wb = W1 + (size_t)e * DIM * FDIM + n0;
    for (int k0 = 0; k0 < DIM; k0 += 16) {
        if (tid < 256) {
            #pragma unroll
            for (int j = 0; j < 2; j++) {
                int q = tid + j * 256;
                int m = q >> 2, kq = q & 3;
                float4 v = *(const float4*)(x + (size_t)toks[m] * DIM + k0 + kq * 4);
                As[(kq * 4 + 0) * 132 + m] = v.x; As[(kq * 4 + 1) * 132 + m] = v.y;
                As[(kq * 4 + 2) * 132 + m] = v.z; As[(kq * 4 + 3) * 132 + m] = v.w;
            }
            #pragma unroll
            for (int j = 0; j < 2; j++) {
                int q = tid + j * 256;
                int kk = q >> 5, nq = q & 31;
                float4 v = *(const float4*)(Wb + (size_t)(k0 + kk) * FDIM + nq * 4);
                *(float4*)&Bs[kk * 132 + nq * 4] = v;
            }
        }
        __syncthreads();
        if (tid < 256) {
            #pragma unroll
            for (int k = 0; k < 16; k++) {
                float4 a0 = *(float4*)&As[k * 132 + ty * 4];
                float4 a1 = *(float4*)&As[k * 132 + 64 + ty * 4];
                float4 b0 = *(float4*)&Bs[k * 132 + tx * 4];
                float4 b1r = *(float4*)&Bs[k * 132 + 64 + tx * 4];
                unsigned long long bb[4];
                bb[0] = ((const unsigned long long*)&b0)[0];
                bb[1] = ((const unsigned long long*)&b0)[1];
                bb[2] = ((const unsigned long long*)&b1r)[0];
                bb[3] = ((const unsigned long long*)&b1r)[1];
                float av[8] = {a0.x, a0.y, a0.z, a0.w, a1.x, a1.y, a1.z, a1.w};
                #pragma unroll
                for (int i = 0; i < 8; i++) {
                    unsigned long long aa = pack2(av[i]);
                    #pragma unroll
                    for (int jj = 0; jj < 4; jj++) acc[i][jj] = fma2(aa, bb[jj], acc[i][jj]);
                }
            }
        }
        __syncthreads();
    }
    if (tid < 256) {
        #pragma unroll
        for (int i = 0; i < 8; i++) {
            int mloc = (i < 4) ? (ty * 4 + i) : (64 + ty * 4 + (i - 4));
            int mi = m0 + mloc;
            if (mi >= count) continue;
            float* Hrow = g_H + (size_t)(base + mi) * FDIM + n0;
            #pragma unroll
            for (int jj = 0; jj < 4; jj++) {
                int nloc = (jj < 2) ? (tx * 4 + jj * 2) : (64 + tx * 4 + (jj - 2) * 2);
                float2 v = *(float2*)&acc[i][jj];
                float h0 = gelu_f(v.x + b1[e * FDIM + n0 + nloc]);
                float h1 = gelu_f(v.y + b1[e * FDIM + n0 + nloc + 1]);
                *(float2*)(Hrow + nloc) = make_float2(h0, h1);
            }
        }
    }
#endif
}

// ==================== GEMM2: out += gate * (H @ W2[e] + b2[e]) ====================
__global__ __launch_bounds__(NTHREADS, 2)
void k_gemm2(const float* __restrict__ W2, const float* __restrict__ b2,
             float* __restrict__ out) {
    const int e = blockIdx.z;
    const int count = g_cnt[e];
    const int m0 = blockIdx.y * TM;
    if (m0 >= count) return;
    const int n0 = blockIdx.x * TN;
    const int tid = threadIdx.x;
    const int wid = tid >> 5, lane = tid & 31;
    extern __shared__ char dynraw[];
    __shared__ int   toks[TM];
    __shared__ float gts[TM];
    __shared__ int s_base;
    if (tid < TM) {
        int mi = min(m0 + tid, count - 1);
        toks[tid] = g_tok[e][mi];
        gts[tid]  = g_gate[e][mi];
    }
    if (tid == 0) {
        int b = 0;
        for (int i = 0; i < e; i++) b += g_cnt[i];
        s_base = b;
    }

#if USE_TC
    __shared__ __align__(8) unsigned long long s_bar[3 * NSTG];
    __shared__ uint32_t s_tmem;
    __shared__ const float* s_arows[TM];
    const uint32_t sm = (sm2u32(dynraw) + 1023u) & ~1023u;
    if (tid == 0) {
        for (int s = 0; s < NSTG; s++) {
            mbar_init(sm2u32(&s_bar[s]), 1);
            mbar_init(sm2u32(&s_bar[NSTG + s]), 128);
            mbar_init(sm2u32(&s_bar[2 * NSTG + s]), 128);
        }
    }
    if (wid == 0) {
        asm volatile("tcgen05.alloc.cta_group::1.sync.aligned.shared::cta.b32 [%0], %1;"
                     :: "r"(sm2u32(&s_tmem)), "r"((uint32_t)TMEM_NCOLS) : "memory");
        asm volatile("tcgen05.relinquish_alloc_permit.cta_group::1.sync.aligned;");
    }
    __syncthreads();
    if (tid < TM) s_arows[tid] = g_H + (size_t)(s_base + min(m0 + tid, count - 1)) * FDIM;
    __syncthreads();
    const uint32_t tmem = s_tmem;
    const uint32_t mb_done = sm2u32(&s_bar[0]);
    const uint32_t mb_fa   = sm2u32(&s_bar[NSTG]);
    const uint32_t mb_fb   = sm2u32(&s_bar[2 * NSTG]);

    const int NC = FDIM / KC;   // 64
    gemm_mainloop(s_arows, W2 + (size_t)e * FDIM * DIM + n0, DIM,
                  NC, sm, tmem, mb_done, mb_fa, mb_fb);
    __syncthreads();
    mbar_wait(mb_done + ((NC - 1) & (NSTG - 1)) * 8, ((NC - 1) >> 2) & 1);
    asm volatile("tcgen05.fence::after_thread_sync;" ::: "memory");

    if (wid < 8) {
        const int sp = wid & 3, half = wid >> 2;
        const int ml = sp * 32 + lane;
        const int mi = m0 + ml;
        const bool valid = mi < count;
        const int tok = toks[ml];
        const float gate = gts[ml];
        float* orow = out + (size_t)tok * DIM + n0;
        const float* bp = b2 + (size_t)e * DIM + n0;
        #pragma unroll
        for (int cb = 0; cb < 2; cb++) {
            const uint32_t c0 = half * 64 + cb * 32;
            uint32_t rg[32];
            LDTM32(rg, tmem + TM_D + c0);
            asm volatile("tcgen05.wait::ld.sync.aligned;" ::: "memory");
            if (valid) {
                #pragma unroll
                for (int i = 0; i < 32; i++) {
                    float y = __uint_as_float(rg[i]) + bp[c0 + i];
                    atomicAdd(orow + c0 + i, gate * y);
                }
            }
        }
        asm volatile("tcgen05.fence::before_thread_sync;" ::: "memory");
    }
    __syncthreads();
    if (tid == 0)
        for (int s = 0; s < 3 * NSTG; s++) mbar_inval(sm2u32(&s_bar[s]));
    if (wid == 0) {
        asm volatile("tcgen05.dealloc.cta_group::1.sync.aligned.b32 %0, %1;"
                     :: "r"(tmem), "r"((uint32_t)TMEM_NCOLS));
    }
#else
    // ---------- FFMA f32x2 fallback (tid<256 active) ----------
    float* As = (float*)dynraw;
    float* Bs = As + 16 * 132;
    __syncthreads();
    const int base = s_base;
    const int tx = tid & 15, ty = tid >> 4;
    unsigned long long acc[8][4];
    #pragma unroll
    for (int i = 0; i < 8; i++)
        #pragma unroll
        for (int j = 0; j < 4; j++) acc[i][j] = 0ull;
    const float* Wb = W2 + (size_t)e * FDIM * DIM + n0;
    for (int k0 = 0; k0 < FDIM; k0 += 16) {
        if (tid < 256) {
            #pragma unroll
            for (int j = 0; j < 2; j++) {
                int q = tid + j * 256;
                int m = q >> 2, kq = q & 3;
                int rowg = base + min(m0 + m, count - 1);
                float4 v = *(const float4*)(g_H + (size_t)rowg * FDIM + k0 + kq * 4);
                As[(kq * 4 + 0) * 132 + m] = v.x; As[(kq * 4 + 1) * 132 + m] = v.y;
                As[(kq * 4 + 2) * 132 + m] = v.z; As[(kq * 4 + 3) * 132 + m] = v.w;
            }
            #pragma unroll
            for (int j = 0; j < 2; j++) {
                int q = tid + j * 256;
                int kk = q >> 5, nq = q & 31;
                float4 v = *(const float4*)(Wb + (size_t)(k0 + kk) * DIM + nq * 4);
                *(float4*)&Bs[kk * 132 + nq * 4] = v;
            }
        }
        __syncthreads();
        if (tid < 256) {
            #pragma unroll
            for (int k = 0; k < 16; k++) {
                float4 a0 = *(float4*)&As[k * 132 + ty * 4];
                float4 a1 = *(float4*)&As[k * 132 + 64 + ty * 4];
                float4 b0 = *(float4*)&Bs[k * 132 + tx * 4];
                float4 b1r = *(float4*)&Bs[k * 132 + 64 + tx * 4];
                unsigned long long bb[4];
                bb[0] = ((const unsigned long long*)&b0)[0];
                bb[1] = ((const unsigned long long*)&b0)[1];
                bb[2] = ((const unsigned long long*)&b1r)[0];
                bb[3] = ((const unsigned long long*)&b1r)[1];
                float av[8] = {a0.x, a0.y, a0.z, a0.w, a1.x, a1.y, a1.z, a1.w};
                #pragma unroll
                for (int i = 0; i < 8; i++) {
                    unsigned long long aa = pack2(av[i]);
                    #pragma unroll
                    for (int jj = 0; jj < 4; jj++) acc[i][jj] = fma2(aa, bb[jj], acc[i][jj]);
                }
            }
        }
        __syncthreads();
    }
    if (tid < 256) {
        #pragma unroll
        for (int i = 0; i < 8; i++) {
            int mloc = (i < 4) ? (ty * 4 + i) : (64 + ty * 4 + (i - 4));
            int mi = m0 + mloc;
            if (mi >= count) continue;
            int tok = toks[mloc];
            float g = gts[mloc];
            float* orow = out + (size_t)tok * DIM + n0;
            #pragma unroll
            for (int jj = 0; jj < 4; jj++) {
                int nloc = (jj < 2) ? (tx * 4 + jj * 2) : (64 + tx * 4 + (jj - 2) * 2);
                float2 v = *(float2*)&acc[i][jj];
                atomicAdd(orow + nloc,     g * (v.x + b2[e * DIM + n0 + nloc]));
                atomicAdd(orow + nloc + 1, g * (v.y + b2[e * DIM + n0 + nloc + 1]));
            }
        }
    }
#endif
}

// ==================== launch ====================
extern "C" void kernel_launch(void* const* d_in, const int* in_sizes, int n_in,
                              void* d_out, int out_size) {
    const float* x       = (const float*)d_in[0];
    const float* anchors = (const float*)d_in[1];
    const float* W1      = (const float*)d_in[2];
    const float* b1      = (const float*)d_in[3];
    const float* W2      = (const float*)d_in[4];
    const float* b2      = (const float*)d_in[5];
    float* out = (float*)d_out;

    static int attr_done = 0;
    if (!attr_done) {
        cudaFuncSetAttribute(k_gemm1, cudaFuncAttributeMaxDynamicSharedMemorySize, SMEM_DYN);
        cudaFuncSetAttribute(k_gemm2, cudaFuncAttributeMaxDynamicSharedMemorySize, SMEM_DYN);
        attr_done = 1;
    }

    const int OUT_END = T_TOK * DIM;
    const int AN_END  = OUT_END + NEXP * DIM;
    const int SC_END  = AN_END + T_TOK * NEXP;
    const int IX_END  = SC_END + T_TOK * 2;
    int write_an = (out_size >= AN_END) ? 1 : 0;
    int wflags = ((out_size >= SC_END) ? 1 : 0) | ((out_size >= IX_END) ? 2 : 0);

    k_anchors<<<1, 256>>>(anchors, out + OUT_END, write_an);
    k_route<<<512, 256>>>(x, out, out + AN_END, out + SC_END, wflags);
    dim3 g1(FDIM / TN, T_TOK / TM, NEXP);
    k_gemm1<<<g1, NTHREADS, SMEM_DYN>>>(x, W1, b1);
    dim3 g2(DIM / TN, T_TOK / TM, NEXP);
    k_gemm2<<<g2, NTHREADS, SMEM_DYN>>>(W2, b2, out);
}